// round 13
// baseline (speedup 1.0000x reference)
#include <cuda_runtime.h>
#include <cuda_bf16.h>
#include <cuda_fp16.h>
#include <math.h>
#include <float.h>
#include <stdint.h>

// ---------------- problem constants ----------------
#define T_TOK 8192
#define HD    2048
#define ID    1024
#define KQ    8
#define NE    128
#define KI    8192
#define I2    2048

// ---------------- fp32 scratch ----------------
__device__ float g_logits[1048576];  // [T, NE]
__device__ float g_wk[65536];        // [T, KQ]
__device__ float g_mix[1024];        // [NE, KQ]

// ---------------- fp16 scratch ----------------
__device__ __half h_x[16777216];                    // x [T,HD]
__device__ __half h_wg[16777216];                   // w_gate [HD,KI]
__device__ __half h_wu[16777216];                   // w_up
__device__ __half h_wd[2097152];                    // w_down [ID,HD]
__device__ __half h_sgw[4194304];                   // shared_w_gate [HD,I2]
__device__ __half h_suw[4194304];                   // shared_w_up
__device__ __half h_sdw[4194304];                   // shared_w_down [I2,HD]
__device__ __half h_gate[67108864];                 // gate pre-act [T,KI]
__device__ __half h_up[67108864];                   // up [T,KI]
__device__ __half h_sgo[16777216];                  // shared gate out [T,I2]
__device__ __half h_suo[16777216];                  // shared up out [T,I2]
__device__ __half h_z[8388608];                     // z [T,ID]
__device__ __half h_h[16777216];                    // h [T,I2]

// bf16 (router only)
__device__ __nv_bfloat16 g_xh[16777216], g_xl[16777216];
__device__ __nv_bfloat16 g_wrh[262144],  g_wrl[262144];

// ================= low-level helpers =================
__device__ __forceinline__ uint32_t smem_u32(const void* p) {
    uint32_t a;
    asm("{ .reg .u64 t; cvta.to.shared.u64 t, %1; cvt.u32.u64 %0, t; }" : "=r"(a) : "l"(p));
    return a;
}
__device__ __forceinline__ void cp16(uint32_t dst, const void* src) {
    asm volatile("cp.async.cg.shared.global [%0], [%1], 16;" :: "r"(dst), "l"(src));
}
__device__ __forceinline__ void cp_commit() {
    asm volatile("cp.async.commit_group;" ::: "memory");
}
template<int N> __device__ __forceinline__ void cp_wait() {
    asm volatile("cp.async.wait_group %0;" :: "n"(N) : "memory");
}
__device__ __forceinline__ void ldsm4(uint32_t* r, uint32_t addr) {
    asm volatile("ldmatrix.sync.aligned.m8n8.x4.shared.b16 {%0,%1,%2,%3}, [%4];"
                 : "=r"(r[0]), "=r"(r[1]), "=r"(r[2]), "=r"(r[3]) : "r"(addr));
}
__device__ __forceinline__ void ldsm4t(uint32_t* r, uint32_t addr) {
    asm volatile("ldmatrix.sync.aligned.m8n8.x4.trans.shared.b16 {%0,%1,%2,%3}, [%4];"
                 : "=r"(r[0]), "=r"(r[1]), "=r"(r[2]), "=r"(r[3]) : "r"(addr));
}
__device__ __forceinline__ void mma_bf16(float* d, const uint32_t* a, uint32_t b0, uint32_t b1) {
    asm volatile("mma.sync.aligned.m16n8k16.row.col.f32.bf16.bf16.f32 "
                 "{%0,%1,%2,%3}, {%4,%5,%6,%7}, {%8,%9}, {%0,%1,%2,%3};"
                 : "+f"(d[0]), "+f"(d[1]), "+f"(d[2]), "+f"(d[3])
                 : "r"(a[0]), "r"(a[1]), "r"(a[2]), "r"(a[3]), "r"(b0), "r"(b1));
}
__device__ __forceinline__ void mma_f16(float* d, const uint32_t* a, uint32_t b0, uint32_t b1) {
    asm volatile("mma.sync.aligned.m16n8k16.row.col.f32.f16.f16.f32 "
                 "{%0,%1,%2,%3}, {%4,%5,%6,%7}, {%8,%9}, {%0,%1,%2,%3};"
                 : "+f"(d[0]), "+f"(d[1]), "+f"(d[2]), "+f"(d[3])
                 : "r"(a[0]), "r"(a[1]), "r"(a[2]), "r"(a[3]), "r"(b0), "r"(b1));
}

#define BM 128
#define BK 64
#define A_STR 144
#define SA_HALF (BM * A_STR)

// ================= fp16 single-pass GEMM, fp16 output, dual-B via grid.z =================
// 3-stage cp.async pipeline.
template<int BN_T>
__global__ __launch_bounds__(512, 1)
void hmma1h_kernel(const __half* __restrict__ A,
                   const __half* __restrict__ B0, const __half* __restrict__ B1,
                   __half* __restrict__ C0, __half* __restrict__ C1, int N, int Kd)
{
    constexpr int WN      = BN_T / 4;
    constexpr int NH      = BN_T / 64;
    constexpr int B_STR_T = BN_T * 2 + 16;
    constexpr int SB      = BK * B_STR_T;
    constexpr int STAGEB  = SA_HALF + SB;
    constexpr int NBCH    = BN_T / 8;
    constexpr int B_ITERS = (BK * NBCH) / 512;

    const __half* B = blockIdx.z ? B1 : B0;
    __half*       C = blockIdx.z ? C1 : C0;

    extern __shared__ char smem[];
    const uint32_t sb = smem_u32(smem);
    const int tid  = threadIdx.x;
    const int lane = tid & 31;
    const int wid  = tid >> 5;
    const int wr   = wid & 3;
    const int wc   = wid >> 2;
    const int row0 = blockIdx.x * BM;
    const int col0 = blockIdx.y * BN_T;
    const int nch  = Kd >> 6;

    float accf[2][2 * NH][4];
#pragma unroll
    for (int i = 0; i < 2; i++)
#pragma unroll
        for (int j = 0; j < 2 * NH; j++)
#pragma unroll
            for (int q = 0; q < 4; q++) accf[i][j][q] = 0.f;

    auto load_stage = [&](int stg, int k0) {
        uint32_t s0 = sb + stg * STAGEB;
#pragma unroll
        for (int it = 0; it < 2; it++) {
            int idx = it * 512 + tid;
            int r = idx >> 3, c = idx & 7;
            cp16(s0 + r * A_STR + c * 16, A + (size_t)(row0 + r) * Kd + k0 + c * 8);
        }
#pragma unroll
        for (int it = 0; it < B_ITERS; it++) {
            int idx = it * 512 + tid;
            int r = idx / NBCH, c = idx % NBCH;
            cp16(s0 + SA_HALF + r * B_STR_T + c * 16, B + (size_t)(k0 + r) * N + col0 + c * 8);
        }
        cp_commit();
    };

    load_stage(0, 0);
    load_stage(1, 64);

    const int a_row  = wr * 32 + (lane & 15);
    const int a_colb = (lane >> 4) << 4;
    const int b_row  = lane & 15;
    const int b_colb = (wc * WN + ((lane >> 4) << 3)) * 2;

    int stg = 0;
    for (int ch = 0; ch < nch; ch++) {
        if (ch + 1 < nch) cp_wait<1>(); else cp_wait<0>();
        __syncthreads();
        if (ch + 2 < nch) {
            int ns = stg + 2; if (ns >= 3) ns -= 3;
            load_stage(ns, (ch + 2) << 6);
        }

        uint32_t sA = sb + stg * STAGEB;
        uint32_t sB = sA + SA_HALF;

#pragma unroll
        for (int ks = 0; ks < 4; ks++) {
            const int k16 = ks << 4;
            uint32_t Af[2][4];
#pragma unroll
            for (int mi = 0; mi < 2; mi++)
                ldsm4(Af[mi], sA + (a_row + mi * 16) * A_STR + k16 * 2 + a_colb);
#pragma unroll
            for (int nh = 0; nh < NH; nh++) {
                uint32_t Bf[4];
                ldsm4t(Bf, sB + (b_row + k16) * B_STR_T + b_colb + nh * 32);
#pragma unroll
                for (int mi = 0; mi < 2; mi++)
#pragma unroll
                    for (int q = 0; q < 2; q++)
                        mma_f16(accf[mi][nh * 2 + q], Af[mi], Bf[q * 2], Bf[q * 2 + 1]);
            }
        }
        stg++; if (stg >= 3) stg = 0;
    }

    const int er = row0 + wr * 32 + (lane >> 2);
    const int ec = col0 + wc * WN + (lane & 3) * 2;
#pragma unroll
    for (int mi = 0; mi < 2; mi++)
#pragma unroll
        for (int ni = 0; ni < 2 * NH; ni++) {
            __half* p0 = C + (size_t)(er + mi * 16) * N + ec + ni * 8;
            __half* p1 = p0 + 8 * N;
            *(__half2*)p0 = __floats2half2_rn(accf[mi][ni][0], accf[mi][ni][1]);
            *(__half2*)p1 = __floats2half2_rn(accf[mi][ni][2], accf[mi][ni][3]);
        }
}
#define SMEM_S256 (3 * (SA_HALF + BK * (256 * 2 + 16)))   // 156672

// ================= fp16 single-pass GEMM, fp32 output (+optional acc), 3-stage =================
template<int BN_T>
__global__ __launch_bounds__(512, 1)
void hmma1f_kernel(const __half* __restrict__ A, const __half* __restrict__ B,
                   float* __restrict__ C, int N, int Kd, int acc)
{
    constexpr int WN      = BN_T / 4;
    constexpr int NH      = BN_T / 64;
    constexpr int B_STR_T = BN_T * 2 + 16;
    constexpr int SB      = BK * B_STR_T;
    constexpr int STAGEB  = SA_HALF + SB;
    constexpr int NBCH    = BN_T / 8;
    constexpr int B_ITERS = (BK * NBCH) / 512;

    extern __shared__ char smem[];
    const uint32_t sb = smem_u32(smem);
    const int tid  = threadIdx.x;
    const int lane = tid & 31;
    const int wid  = tid >> 5;
    const int wr   = wid & 3;
    const int wc   = wid >> 2;
    const int row0 = blockIdx.x * BM;
    const int col0 = blockIdx.y * BN_T;
    const int nch  = Kd >> 6;

    float accf[2][2 * NH][4];
#pragma unroll
    for (int i = 0; i < 2; i++)
#pragma unroll
        for (int j = 0; j < 2 * NH; j++)
#pragma unroll
            for (int q = 0; q < 4; q++) accf[i][j][q] = 0.f;

    auto load_stage = [&](int stg, int k0) {
        uint32_t s0 = sb + stg * STAGEB;
#pragma unroll
        for (int it = 0; it < 2; it++) {
            int idx = it * 512 + tid;
            int r = idx >> 3, c = idx & 7;
            cp16(s0 + r * A_STR + c * 16, A + (size_t)(row0 + r) * Kd + k0 + c * 8);
        }
#pragma unroll
        for (int it = 0; it < B_ITERS; it++) {
            int idx = it * 512 + tid;
            int r = idx / NBCH, c = idx % NBCH;
            cp16(s0 + SA_HALF + r * B_STR_T + c * 16, B + (size_t)(k0 + r) * N + col0 + c * 8);
        }
        cp_commit();
    };

    load_stage(0, 0);
    load_stage(1, 64);

    const int a_row  = wr * 32 + (lane & 15);
    const int a_colb = (lane >> 4) << 4;
    const int b_row  = lane & 15;
    const int b_colb = (wc * WN + ((lane >> 4) << 3)) * 2;

    int stg = 0;
    for (int ch = 0; ch < nch; ch++) {
        if (ch + 1 < nch) cp_wait<1>(); else cp_wait<0>();
        __syncthreads();
        if (ch + 2 < nch) {
            int ns = stg + 2; if (ns >= 3) ns -= 3;
            load_stage(ns, (ch + 2) << 6);
        }

        uint32_t sA = sb + stg * STAGEB;
        uint32_t sB = sA + SA_HALF;

#pragma unroll
        for (int ks = 0; ks < 4; ks++) {
            const int k16 = ks << 4;
            uint32_t Af[2][4];
#pragma unroll
            for (int mi = 0; mi < 2; mi++)
                ldsm4(Af[mi], sA + (a_row + mi * 16) * A_STR + k16 * 2 + a_colb);
#pragma unroll
            for (int nh = 0; nh < NH; nh++) {
                uint32_t Bf[4];
                ldsm4t(Bf, sB + (b_row + k16) * B_STR_T + b_colb + nh * 32);
#pragma unroll
                for (int mi = 0; mi < 2; mi++)
#pragma unroll
                    for (int q = 0; q < 2; q++)
                        mma_f16(accf[mi][nh * 2 + q], Af[mi], Bf[q * 2], Bf[q * 2 + 1]);
            }
        }
        stg++; if (stg >= 3) stg = 0;
    }

    const int er = row0 + wr * 32 + (lane >> 2);
    const int ec = col0 + wc * WN + (lane & 3) * 2;
#pragma unroll
    for (int mi = 0; mi < 2; mi++)
#pragma unroll
        for (int ni = 0; ni < 2 * NH; ni++) {
            float* p0 = C + (size_t)(er + mi * 16) * N + ec + ni * 8;
            float* p1 = p0 + 8 * N;
            float v0 = accf[mi][ni][0], v1 = accf[mi][ni][1];
            float v2 = accf[mi][ni][2], v3 = accf[mi][ni][3];
            if (acc) {
                float2 o0 = *(float2*)p0, o1 = *(float2*)p1;
                v0 += o0.x; v1 += o0.y; v2 += o1.x; v3 += o1.y;
            }
            *(float2*)p0 = make_float2(v0, v1);
            *(float2*)p1 = make_float2(v2, v3);
        }
}

// ================= bf16 hi/lo 3-pass GEMM (router only, 2-stage) =================
template<int BN_T>
__global__ __launch_bounds__(512, 1)
void hmma3_kernel(const __nv_bfloat16* __restrict__ Ah, const __nv_bfloat16* __restrict__ Al,
                  const __nv_bfloat16* __restrict__ Bh, const __nv_bfloat16* __restrict__ Bl,
                  float* __restrict__ C, int N, int Kd)
{
    constexpr int WN      = BN_T / 4;
    constexpr int NH      = BN_T / 64;
    constexpr int B_STR_T = BN_T * 2 + 16;
    constexpr int SB_HALF = BK * B_STR_T;
    constexpr int STAGEB  = 2 * SA_HALF + 2 * SB_HALF;
    constexpr int NBCH    = BN_T / 8;
    constexpr int B_ITERS = (BK * NBCH) / 512;

    extern __shared__ char smem[];
    const uint32_t sb = smem_u32(smem);
    const int tid  = threadIdx.x;
    const int lane = tid & 31;
    const int wid  = tid >> 5;
    const int wr   = wid & 3;
    const int wc   = wid >> 2;
    const int row0 = blockIdx.x * BM;
    const int col0 = blockIdx.y * BN_T;
    const int nch  = Kd >> 6;

    float accf[2][2 * NH][4];
#pragma unroll
    for (int i = 0; i < 2; i++)
#pragma unroll
        for (int j = 0; j < 2 * NH; j++)
#pragma unroll
            for (int q = 0; q < 4; q++) accf[i][j][q] = 0.f;

    auto load_stage = [&](int stg, int k0) {
        uint32_t s0 = sb + stg * STAGEB;
#pragma unroll
        for (int it = 0; it < 2; it++) {
            int idx = it * 512 + tid;
            int r = idx >> 3, c = idx & 7;
            const __nv_bfloat16* gh = Ah + (size_t)(row0 + r) * Kd + k0 + c * 8;
            const __nv_bfloat16* gl = Al + (size_t)(row0 + r) * Kd + k0 + c * 8;
            uint32_t d = s0 + r * A_STR + c * 16;
            cp16(d, gh);
            cp16(d + SA_HALF, gl);
        }
#pragma unroll
        for (int it = 0; it < B_ITERS; it++) {
            int idx = it * 512 + tid;
            int r = idx / NBCH, c = idx % NBCH;
            const __nv_bfloat16* gh = Bh + (size_t)(k0 + r) * N + col0 + c * 8;
            const __nv_bfloat16* gl = Bl + (size_t)(k0 + r) * N + col0 + c * 8;
            uint32_t d = s0 + 2 * SA_HALF + r * B_STR_T + c * 16;
            cp16(d, gh);
            cp16(d + SB_HALF, gl);
        }
        cp_commit();
    };

    load_stage(0, 0);

    const int a_row  = wr * 32 + (lane & 15);
    const int a_colb = (lane >> 4) << 4;
    const int b_row  = lane & 15;
    const int b_colb = (wc * WN + ((lane >> 4) << 3)) * 2;

    for (int ch = 0; ch < nch; ch++) {
        cp_wait<0>();
        __syncthreads();
        if (ch + 1 < nch) load_stage((ch + 1) & 1, (ch + 1) << 6);

        uint32_t sA = sb + (ch & 1) * STAGEB;
        uint32_t sB = sA + 2 * SA_HALF;

#pragma unroll
        for (int ks = 0; ks < 4; ks++) {
            const int k16 = ks << 4;
            uint32_t Ahf[2][4], Alf[2][4];
#pragma unroll
            for (int mi = 0; mi < 2; mi++) {
                uint32_t ad = sA + (a_row + mi * 16) * A_STR + k16 * 2 + a_colb;
                ldsm4(Ahf[mi], ad);
                ldsm4(Alf[mi], ad + SA_HALF);
            }
#pragma unroll
            for (int nh = 0; nh < NH; nh++) {
                uint32_t Bhf[4], Blf[4];
                uint32_t bd = sB + (b_row + k16) * B_STR_T + b_colb + nh * 32;
                ldsm4t(Bhf, bd);
                ldsm4t(Blf, bd + SB_HALF);
#pragma unroll
                for (int mi = 0; mi < 2; mi++)
#pragma unroll
                    for (int q = 0; q < 2; q++) {
                        float* d = accf[mi][nh * 2 + q];
                        mma_bf16(d, Ahf[mi], Bhf[q * 2], Bhf[q * 2 + 1]);
                        mma_bf16(d, Alf[mi], Bhf[q * 2], Bhf[q * 2 + 1]);
                        mma_bf16(d, Ahf[mi], Blf[q * 2], Blf[q * 2 + 1]);
                    }
            }
        }
    }

    const int er = row0 + wr * 32 + (lane >> 2);
    const int ec = col0 + wc * WN + (lane & 3) * 2;
#pragma unroll
    for (int mi = 0; mi < 2; mi++)
#pragma unroll
        for (int ni = 0; ni < 2 * NH; ni++) {
            float* p0 = C + (size_t)(er + mi * 16) * N + ec + ni * 8;
            float* p1 = p0 + 8 * N;
            *(float2*)p0 = make_float2(accf[mi][ni][0], accf[mi][ni][1]);
            *(float2*)p1 = make_float2(accf[mi][ni][2], accf[mi][ni][3]);
        }
}
#define SMEM_128 (2 * (2 * SA_HALF + 2 * (BK * (128 * 2 + 16))))

// ================= conversions =================
__global__ void convx_kernel(const float4* __restrict__ src, __half* __restrict__ xh,
                             __nv_bfloat16* __restrict__ bh, __nv_bfloat16* __restrict__ bl, int n4)
{
    int i = blockIdx.x * 256 + threadIdx.x;
    if (i >= n4) return;
    float4 v = src[i];
    __half2* dp = (__half2*)(xh + i * 4);
    dp[0] = __floats2half2_rn(v.x, v.y);
    dp[1] = __floats2half2_rn(v.z, v.w);
    __nv_bfloat16 h0 = __float2bfloat16_rn(v.x), h1 = __float2bfloat16_rn(v.y);
    __nv_bfloat16 h2 = __float2bfloat16_rn(v.z), h3 = __float2bfloat16_rn(v.w);
    __nv_bfloat162 hh0 = {h0, h1}, hh1 = {h2, h3};
    __nv_bfloat162 ll0 = {__float2bfloat16_rn(v.x - __bfloat162float(h0)),
                          __float2bfloat16_rn(v.y - __bfloat162float(h1))};
    __nv_bfloat162 ll1 = {__float2bfloat16_rn(v.z - __bfloat162float(h2)),
                          __float2bfloat16_rn(v.w - __bfloat162float(h3))};
    *(__nv_bfloat162*)(bh + i * 4)     = hh0;
    *(__nv_bfloat162*)(bh + i * 4 + 2) = hh1;
    *(__nv_bfloat162*)(bl + i * 4)     = ll0;
    *(__nv_bfloat162*)(bl + i * 4 + 2) = ll1;
}

__global__ void conv1_kernel(const float4* __restrict__ src, __half* __restrict__ dst, int n4)
{
    int i = blockIdx.x * 256 + threadIdx.x;
    if (i >= n4) return;
    float4 v = src[i];
    __half2* dp = (__half2*)(dst + i * 4);
    dp[0] = __floats2half2_rn(v.x, v.y);
    dp[1] = __floats2half2_rn(v.z, v.w);
}

__global__ void split_kernel(const float4* __restrict__ src,
                             __nv_bfloat16* __restrict__ hi,
                             __nv_bfloat16* __restrict__ lo, int n4)
{
    int i = blockIdx.x * 256 + threadIdx.x;
    if (i >= n4) return;
    float4 v = src[i];
    __nv_bfloat16 h0 = __float2bfloat16_rn(v.x), h1 = __float2bfloat16_rn(v.y);
    __nv_bfloat16 h2 = __float2bfloat16_rn(v.z), h3 = __float2bfloat16_rn(v.w);
    __nv_bfloat162 hh0 = {h0, h1}, hh1 = {h2, h3};
    __nv_bfloat162 ll0 = {__float2bfloat16_rn(v.x - __bfloat162float(h0)),
                          __float2bfloat16_rn(v.y - __bfloat162float(h1))};
    __nv_bfloat162 ll1 = {__float2bfloat16_rn(v.z - __bfloat162float(h2)),
                          __float2bfloat16_rn(v.w - __bfloat162float(h3))};
    *(__nv_bfloat162*)(hi + i * 4)     = hh0;
    *(__nv_bfloat162*)(hi + i * 4 + 2) = hh1;
    *(__nv_bfloat162*)(lo + i * 4)     = ll0;
    *(__nv_bfloat162*)(lo + i * 4 + 2) = ll1;
}

// ================= amplitudes -> normalized mix =================
__global__ void mix_kernel(const float* __restrict__ amp)
{
    int e = threadIdx.x;
    if (e >= NE) return;
    float p[KQ];
    float s = 0.f;
#pragma unroll
    for (int k = 0; k < KQ; k++) {
        float a0 = amp[(e * KQ + k) * 2 + 0];
        float a1 = amp[(e * KQ + k) * 2 + 1];
        p[k] = a0 * a0 + a1 * a1;
        s += p[k];
    }
    float inv = 1.f / (s + 1e-8f);
#pragma unroll
    for (int k = 0; k < KQ; k++) g_mix[e * KQ + k] = p[k] * inv;
}

// ================= softmax + top-4 + collapse =================
__global__ void topk_kernel(const float* __restrict__ expert_scale)
{
    int lane = threadIdx.x & 31;
    int warp = threadIdx.x >> 5;
    int t = blockIdx.x * 8 + warp;
    const float* lrow = g_logits + (size_t)t * NE;

    float v[4];
#pragma unroll
    for (int j = 0; j < 4; j++) v[j] = lrow[lane + 32 * j];

    float m = fmaxf(fmaxf(v[0], v[1]), fmaxf(v[2], v[3]));
#pragma unroll
    for (int o = 16; o; o >>= 1) m = fmaxf(m, __shfl_xor_sync(0xffffffffu, m, o));

    float D = 0.f;
#pragma unroll
    for (int j = 0; j < 4; j++) D += expf(v[j] - m);
#pragma unroll
    for (int o = 16; o; o >>= 1) D += __shfl_xor_sync(0xffffffffu, D, o);

    float lv[4] = {v[0], v[1], v[2], v[3]};
    float selv[4];
    int   seli[4];
#pragma unroll
    for (int it = 0; it < 4; it++) {
        float bv = -FLT_MAX;
        int   bi = NE;
#pragma unroll
        for (int j = 0; j < 4; j++) {
            int e = lane + 32 * j;
            if (lv[j] > bv) { bv = lv[j]; bi = e; }
        }
#pragma unroll
        for (int o = 16; o; o >>= 1) {
            float ov = __shfl_xor_sync(0xffffffffu, bv, o);
            int   oi = __shfl_xor_sync(0xffffffffu, bi, o);
            if (ov > bv || (ov == bv && oi < bi)) { bv = ov; bi = oi; }
        }
        selv[it] = bv;
        seli[it] = bi;
        if ((bi & 31) == lane) lv[bi >> 5] = -FLT_MAX;
    }

    float ew[4];
    float S = 0.f;
#pragma unroll
    for (int it = 0; it < 4; it++) { ew[it] = expf(selv[it] - m); S += ew[it]; }
    float denom = S + 1e-8f * D;

    if (lane < KQ) {
        float acc = 0.f;
#pragma unroll
        for (int it = 0; it < 4; it++)
            acc += (ew[it] / denom) * expert_scale[seli[it]] * g_mix[seli[it] * KQ + lane];
        g_wk[t * KQ + lane] = acc;
    }
}

__device__ __forceinline__ float silu_mul(float g, float u) {
    return (g / (1.f + expf(-g))) * u;
}

// ================= z = sum_k wk * silu(gate) * up  (fp16 in, fp16 out) =================
__global__ void moe_mix_kernel()
{
    int t = blockIdx.y;
    int i = (blockIdx.x * 256 + threadIdx.x) * 2;
    __shared__ float w[KQ];
    if (threadIdx.x < KQ) w[threadIdx.x] = g_wk[t * KQ + threadIdx.x];
    __syncthreads();
    float a0 = 0.f, a1 = 0.f;
#pragma unroll
    for (int k = 0; k < KQ; k++) {
        size_t off = (size_t)t * KI + k * ID + i;
        __half2 g2 = *(const __half2*)(h_gate + off);
        __half2 u2 = *(const __half2*)(h_up + off);
        a0 += w[k] * silu_mul(__low2float(g2),  __low2float(u2));
        a1 += w[k] * silu_mul(__high2float(g2), __high2float(u2));
    }
    *(__half2*)(h_z + (size_t)t * ID + i) = __floats2half2_rn(a0, a1);
}

// ================= shared expert elementwise (fp16 in, fp16 out) =================
__global__ void silu_mul_kernel()
{
    size_t idx = ((size_t)blockIdx.x * 256 + threadIdx.x) * 2;
    __half2 g2 = *(const __half2*)(h_sgo + idx);
    __half2 u2 = *(const __half2*)(h_suo + idx);
    *(__half2*)(h_h + idx) = __floats2half2_rn(silu_mul(__low2float(g2),  __low2float(u2)),
                                               silu_mul(__high2float(g2), __high2float(u2)));
}

// ================= host side =================
static void gemm1f(const void* A, const void* B, float* C, int M, int N, int Kd, int acc)
{
    dim3 grid(M / BM, N / 256);
    hmma1f_kernel<256><<<grid, 512, SMEM_S256>>>(
        (const __half*)A, (const __half*)B, C, N, Kd, acc);
}

extern "C" void kernel_launch(void* const* d_in, const int* in_sizes, int n_in,
                              void* d_out, int out_size)
{
    const float* x             = (const float*)d_in[0];
    const float* w_router      = (const float*)d_in[1];
    const float* w_gate        = (const float*)d_in[2];
    const float* w_up          = (const float*)d_in[3];
    const float* w_down        = (const float*)d_in[4];
    const float* amplitudes    = (const float*)d_in[5];
    const float* expert_scale  = (const float*)d_in[6];
    const float* shared_w_gate = (const float*)d_in[7];
    const float* shared_w_up   = (const float*)d_in[8];
    const float* shared_w_down = (const float*)d_in[9];
    float* out = (float*)d_out;

    cudaFuncSetAttribute(hmma1h_kernel<256>, cudaFuncAttributeMaxDynamicSharedMemorySize, SMEM_S256);
    cudaFuncSetAttribute(hmma1f_kernel<256>, cudaFuncAttributeMaxDynamicSharedMemorySize, SMEM_S256);
    cudaFuncSetAttribute(hmma3_kernel<128>, cudaFuncAttributeMaxDynamicSharedMemorySize, SMEM_128);

    void *px, *pwg, *pwu, *pwd, *psgw, *psuw, *psdw;
    void *pga, *pup, *psgo, *psuo, *pz, *ph, *plog;
    void *bxh, *bxl, *bwrh, *bwrl;
    cudaGetSymbolAddress(&px, h_x);
    cudaGetSymbolAddress(&pwg, h_wg);   cudaGetSymbolAddress(&pwu, h_wu);
    cudaGetSymbolAddress(&pwd, h_wd);
    cudaGetSymbolAddress(&psgw, h_sgw); cudaGetSymbolAddress(&psuw, h_suw);
    cudaGetSymbolAddress(&psdw, h_sdw);
    cudaGetSymbolAddress(&pga, h_gate); cudaGetSymbolAddress(&pup, h_up);
    cudaGetSymbolAddress(&psgo, h_sgo); cudaGetSymbolAddress(&psuo, h_suo);
    cudaGetSymbolAddress(&pz, h_z);     cudaGetSymbolAddress(&ph, h_h);
    cudaGetSymbolAddress(&plog, g_logits);
    cudaGetSymbolAddress(&bxh, g_xh);   cudaGetSymbolAddress(&bxl, g_xl);
    cudaGetSymbolAddress(&bwrh, g_wrh); cudaGetSymbolAddress(&bwrl, g_wrl);

    // 1. conversions (x read once -> fp16 + bf16 limbs)
    convx_kernel<<<(T_TOK * HD / 4) / 256, 256>>>((const float4*)x, (__half*)px,
                                                  (__nv_bfloat16*)bxh, (__nv_bfloat16*)bxl, T_TOK * HD / 4);
    conv1_kernel<<<(HD * KI / 4) / 256, 256>>>((const float4*)w_gate, (__half*)pwg, HD * KI / 4);
    conv1_kernel<<<(HD * KI / 4) / 256, 256>>>((const float4*)w_up,   (__half*)pwu, HD * KI / 4);
    conv1_kernel<<<(ID * HD / 4) / 256, 256>>>((const float4*)w_down, (__half*)pwd, ID * HD / 4);
    conv1_kernel<<<(HD * I2 / 4) / 256, 256>>>((const float4*)shared_w_gate, (__half*)psgw, HD * I2 / 4);
    conv1_kernel<<<(HD * I2 / 4) / 256, 256>>>((const float4*)shared_w_up,   (__half*)psuw, HD * I2 / 4);
    conv1_kernel<<<(I2 * HD / 4) / 256, 256>>>((const float4*)shared_w_down, (__half*)psdw, I2 * HD / 4);
    split_kernel<<<(HD * NE / 4) / 256, 256>>>((const float4*)w_router, (__nv_bfloat16*)bwrh, (__nv_bfloat16*)bwrl, HD * NE / 4);

    // 2. router path in bf16x3 (precision-sensitive: top-k selection)
    mix_kernel<<<1, 128>>>(amplitudes);
    hmma3_kernel<128><<<dim3(T_TOK / BM, 1), 512, SMEM_128>>>(
        (const __nv_bfloat16*)bxh, (const __nv_bfloat16*)bxl,
        (const __nv_bfloat16*)bwrh, (const __nv_bfloat16*)bwrl, (float*)plog, NE, HD);
    topk_kernel<<<T_TOK / 8, 256>>>(expert_scale);

    // 3. gate + up projections in ONE launch (grid.z selects B/C)
    hmma1h_kernel<256><<<dim3(T_TOK / BM, KI / 256, 2), 512, SMEM_S256>>>(
        (const __half*)px, (const __half*)pwg, (const __half*)pwu,
        (__half*)pga, (__half*)pup, KI, HD);

    // 4. z = sum_k wk * silu(gate) * up -> fp16
    moe_mix_kernel<<<dim3(ID / 512, T_TOK), 256>>>();

    // 5. down projection: out = z @ w_down
    gemm1f(pz, pwd, out, T_TOK, HD, ID, 0);

    // 6. shared expert gate+up in ONE launch
    hmma1h_kernel<256><<<dim3(T_TOK / BM, I2 / 256, 2), 512, SMEM_S256>>>(
        (const __half*)px, (const __half*)psgw, (const __half*)psuw,
        (__half*)psgo, (__half*)psuo, I2, HD);
    silu_mul_kernel<<<(T_TOK * I2 / 2) / 256, 256>>>();

    // 7. out += h @ shared_w_down
    gemm1f(ph, psdw, out, T_TOK, HD, I2, 1);
}

// round 14
// speedup vs baseline: 1.0221x; 1.0221x over previous
#include <cuda_runtime.h>
#include <cuda_bf16.h>
#include <cuda_fp16.h>
#include <math.h>
#include <float.h>
#include <stdint.h>

// ---------------- problem constants ----------------
#define T_TOK 8192
#define HD    2048
#define ID    1024
#define KQ    8
#define NE    128
#define KI    8192
#define I2    2048

// ---------------- fp32 scratch ----------------
__device__ float g_logits[1048576];  // [T, NE]
__device__ float g_wk[65536];        // [T, KQ]
__device__ float g_mix[1024];        // [NE, KQ]

// ---------------- fp16 scratch ----------------
__device__ __half h_x[16777216];                    // x [T,HD]
__device__ __half h_wg[16777216];                   // w_gate [HD,KI]
__device__ __half h_wu[16777216];                   // w_up
__device__ __half h_wd[2097152];                    // w_down [ID,HD]
__device__ __half h_sgw[4194304];                   // shared_w_gate [HD,I2]
__device__ __half h_suw[4194304];                   // shared_w_up
__device__ __half h_sdw[4194304];                   // shared_w_down [I2,HD]
__device__ __half h_p[67108864];                    // silu(gate)*up [T,KI]
__device__ __half h_z[8388608];                     // z [T,ID]
__device__ __half h_h[16777216];                    // h [T,I2]

// bf16 (router only)
__device__ __nv_bfloat16 g_xh[16777216], g_xl[16777216];
__device__ __nv_bfloat16 g_wrh[262144],  g_wrl[262144];

// ================= low-level helpers =================
__device__ __forceinline__ uint32_t smem_u32(const void* p) {
    uint32_t a;
    asm("{ .reg .u64 t; cvta.to.shared.u64 t, %1; cvt.u32.u64 %0, t; }" : "=r"(a) : "l"(p));
    return a;
}
__device__ __forceinline__ void cp16(uint32_t dst, const void* src) {
    asm volatile("cp.async.cg.shared.global [%0], [%1], 16;" :: "r"(dst), "l"(src));
}
__device__ __forceinline__ void cp_commit() {
    asm volatile("cp.async.commit_group;" ::: "memory");
}
template<int N> __device__ __forceinline__ void cp_wait() {
    asm volatile("cp.async.wait_group %0;" :: "n"(N) : "memory");
}
__device__ __forceinline__ void ldsm4(uint32_t* r, uint32_t addr) {
    asm volatile("ldmatrix.sync.aligned.m8n8.x4.shared.b16 {%0,%1,%2,%3}, [%4];"
                 : "=r"(r[0]), "=r"(r[1]), "=r"(r[2]), "=r"(r[3]) : "r"(addr));
}
__device__ __forceinline__ void ldsm4t(uint32_t* r, uint32_t addr) {
    asm volatile("ldmatrix.sync.aligned.m8n8.x4.trans.shared.b16 {%0,%1,%2,%3}, [%4];"
                 : "=r"(r[0]), "=r"(r[1]), "=r"(r[2]), "=r"(r[3]) : "r"(addr));
}
__device__ __forceinline__ void mma_bf16(float* d, const uint32_t* a, uint32_t b0, uint32_t b1) {
    asm volatile("mma.sync.aligned.m16n8k16.row.col.f32.bf16.bf16.f32 "
                 "{%0,%1,%2,%3}, {%4,%5,%6,%7}, {%8,%9}, {%0,%1,%2,%3};"
                 : "+f"(d[0]), "+f"(d[1]), "+f"(d[2]), "+f"(d[3])
                 : "r"(a[0]), "r"(a[1]), "r"(a[2]), "r"(a[3]), "r"(b0), "r"(b1));
}
__device__ __forceinline__ void mma_f16(float* d, const uint32_t* a, uint32_t b0, uint32_t b1) {
    asm volatile("mma.sync.aligned.m16n8k16.row.col.f32.f16.f16.f32 "
                 "{%0,%1,%2,%3}, {%4,%5,%6,%7}, {%8,%9}, {%0,%1,%2,%3};"
                 : "+f"(d[0]), "+f"(d[1]), "+f"(d[2]), "+f"(d[3])
                 : "r"(a[0]), "r"(a[1]), "r"(a[2]), "r"(a[3]), "r"(b0), "r"(b1));
}

__device__ __forceinline__ float silu_mul(float g, float u) {
    return (g / (1.f + expf(-g))) * u;
}

#define BM 128
#define BK 64
#define A_STR 144
#define SA_HALF (BM * A_STR)

// ================= fused dual-B GEMM: P = silu(A@Bg) * (A@Bu), fp16 out =================
// A [M,Kd], Bg/Bu [Kd,N], P [M,N]. BN=128 per B; per-chunk MMA count = BN256 kernel.
#define GB_STR 272                  // 128*2+16
#define GSB (BK * GB_STR)           // 17408
#define GSTAGE (SA_HALF + 2 * GSB)  // 53248
#define SMEM_GU (2 * GSTAGE)        // 106496

__global__ __launch_bounds__(512, 1)
void hmma_gu_kernel(const __half* __restrict__ A, const __half* __restrict__ Bg,
                    const __half* __restrict__ Bu, __half* __restrict__ P,
                    int N, int Kd)
{
    extern __shared__ char smem[];
    const uint32_t sb = smem_u32(smem);
    const int tid  = threadIdx.x;
    const int lane = tid & 31;
    const int wid  = tid >> 5;
    const int wr   = wid & 3;
    const int wc   = wid >> 2;     // 0..3 over 128 cols -> 32 each
    const int row0 = blockIdx.x * BM;
    const int col0 = blockIdx.y * 128;
    const int nch  = Kd >> 6;

    float accg[2][4][4], accu[2][4][4];
#pragma unroll
    for (int i = 0; i < 2; i++)
#pragma unroll
        for (int j = 0; j < 4; j++)
#pragma unroll
            for (int q = 0; q < 4; q++) { accg[i][j][q] = 0.f; accu[i][j][q] = 0.f; }

    auto load_stage = [&](int stg, int k0) {
        uint32_t s0 = sb + stg * GSTAGE;
#pragma unroll
        for (int it = 0; it < 2; it++) {          // A: 128 rows x 8 chunks
            int idx = it * 512 + tid;
            int r = idx >> 3, c = idx & 7;
            cp16(s0 + r * A_STR + c * 16, A + (size_t)(row0 + r) * Kd + k0 + c * 8);
        }
#pragma unroll
        for (int it = 0; it < 2; it++) {          // Bg+Bu: 64 rows x 16 chunks each
            int idx = it * 512 + tid;
            int r = idx >> 4, c = idx & 15;
            size_t go = (size_t)(k0 + r) * N + col0 + c * 8;
            uint32_t d = s0 + SA_HALF + r * GB_STR + c * 16;
            cp16(d, Bg + go);
            cp16(d + GSB, Bu + go);
        }
        cp_commit();
    };

    load_stage(0, 0);

    const int a_row  = wr * 32 + (lane & 15);
    const int a_colb = (lane >> 4) << 4;
    const int b_row  = lane & 15;
    const int b_colb = (wc * 32 + ((lane >> 4) << 3)) * 2;

    for (int ch = 0; ch < nch; ch++) {
        cp_wait<0>();
        __syncthreads();
        if (ch + 1 < nch) load_stage((ch + 1) & 1, (ch + 1) << 6);

        uint32_t sA  = sb + (ch & 1) * GSTAGE;
        uint32_t sBg = sA + SA_HALF;
        uint32_t sBu = sBg + GSB;

#pragma unroll
        for (int ks = 0; ks < 4; ks++) {
            const int k16 = ks << 4;
            uint32_t Af[2][4];
#pragma unroll
            for (int mi = 0; mi < 2; mi++)
                ldsm4(Af[mi], sA + (a_row + mi * 16) * A_STR + k16 * 2 + a_colb);
#pragma unroll
            for (int nh = 0; nh < 2; nh++) {
                uint32_t Bgf[4], Buf[4];
                uint32_t bo = (b_row + k16) * GB_STR + b_colb + nh * 32;
                ldsm4t(Bgf, sBg + bo);
                ldsm4t(Buf, sBu + bo);
#pragma unroll
                for (int mi = 0; mi < 2; mi++)
#pragma unroll
                    for (int q = 0; q < 2; q++) {
                        mma_f16(accg[mi][nh * 2 + q], Af[mi], Bgf[q * 2], Bgf[q * 2 + 1]);
                        mma_f16(accu[mi][nh * 2 + q], Af[mi], Buf[q * 2], Buf[q * 2 + 1]);
                    }
            }
        }
    }

    const int er = row0 + wr * 32 + (lane >> 2);
    const int ec = col0 + wc * 32 + (lane & 3) * 2;
#pragma unroll
    for (int mi = 0; mi < 2; mi++)
#pragma unroll
        for (int ni = 0; ni < 4; ni++) {
            __half* p0 = P + (size_t)(er + mi * 16) * N + ec + ni * 8;
            __half* p1 = p0 + 8 * N;
            *(__half2*)p0 = __floats2half2_rn(silu_mul(accg[mi][ni][0], accu[mi][ni][0]),
                                              silu_mul(accg[mi][ni][1], accu[mi][ni][1]));
            *(__half2*)p1 = __floats2half2_rn(silu_mul(accg[mi][ni][2], accu[mi][ni][2]),
                                              silu_mul(accg[mi][ni][3], accu[mi][ni][3]));
        }
}

// ================= fp16 single-pass GEMM, fp32 output (+optional acc), 2-stage =================
template<int BN_T>
__global__ __launch_bounds__(512, 1)
void hmma1f_kernel(const __half* __restrict__ A, const __half* __restrict__ B,
                   float* __restrict__ C, int N, int Kd, int acc)
{
    constexpr int WN      = BN_T / 4;
    constexpr int NH      = BN_T / 64;
    constexpr int B_STR_T = BN_T * 2 + 16;
    constexpr int SB      = BK * B_STR_T;
    constexpr int STAGEB  = SA_HALF + SB;
    constexpr int NBCH    = BN_T / 8;
    constexpr int B_ITERS = (BK * NBCH) / 512;

    extern __shared__ char smem[];
    const uint32_t sb = smem_u32(smem);
    const int tid  = threadIdx.x;
    const int lane = tid & 31;
    const int wid  = tid >> 5;
    const int wr   = wid & 3;
    const int wc   = wid >> 2;
    const int row0 = blockIdx.x * BM;
    const int col0 = blockIdx.y * BN_T;
    const int nch  = Kd >> 6;

    float accf[2][2 * NH][4];
#pragma unroll
    for (int i = 0; i < 2; i++)
#pragma unroll
        for (int j = 0; j < 2 * NH; j++)
#pragma unroll
            for (int q = 0; q < 4; q++) accf[i][j][q] = 0.f;

    auto load_stage = [&](int stg, int k0) {
        uint32_t s0 = sb + stg * STAGEB;
#pragma unroll
        for (int it = 0; it < 2; it++) {
            int idx = it * 512 + tid;
            int r = idx >> 3, c = idx & 7;
            cp16(s0 + r * A_STR + c * 16, A + (size_t)(row0 + r) * Kd + k0 + c * 8);
        }
#pragma unroll
        for (int it = 0; it < B_ITERS; it++) {
            int idx = it * 512 + tid;
            int r = idx / NBCH, c = idx % NBCH;
            cp16(s0 + SA_HALF + r * B_STR_T + c * 16, B + (size_t)(k0 + r) * N + col0 + c * 8);
        }
        cp_commit();
    };

    load_stage(0, 0);

    const int a_row  = wr * 32 + (lane & 15);
    const int a_colb = (lane >> 4) << 4;
    const int b_row  = lane & 15;
    const int b_colb = (wc * WN + ((lane >> 4) << 3)) * 2;

    for (int ch = 0; ch < nch; ch++) {
        cp_wait<0>();
        __syncthreads();
        if (ch + 1 < nch) load_stage((ch + 1) & 1, (ch + 1) << 6);

        uint32_t sA = sb + (ch & 1) * STAGEB;
        uint32_t sB = sA + SA_HALF;

#pragma unroll
        for (int ks = 0; ks < 4; ks++) {
            const int k16 = ks << 4;
            uint32_t Af[2][4];
#pragma unroll
            for (int mi = 0; mi < 2; mi++)
                ldsm4(Af[mi], sA + (a_row + mi * 16) * A_STR + k16 * 2 + a_colb);
#pragma unroll
            for (int nh = 0; nh < NH; nh++) {
                uint32_t Bf[4];
                ldsm4t(Bf, sB + (b_row + k16) * B_STR_T + b_colb + nh * 32);
#pragma unroll
                for (int mi = 0; mi < 2; mi++)
#pragma unroll
                    for (int q = 0; q < 2; q++)
                        mma_f16(accf[mi][nh * 2 + q], Af[mi], Bf[q * 2], Bf[q * 2 + 1]);
            }
        }
    }

    const int er = row0 + wr * 32 + (lane >> 2);
    const int ec = col0 + wc * WN + (lane & 3) * 2;
#pragma unroll
    for (int mi = 0; mi < 2; mi++)
#pragma unroll
        for (int ni = 0; ni < 2 * NH; ni++) {
            float* p0 = C + (size_t)(er + mi * 16) * N + ec + ni * 8;
            float* p1 = p0 + 8 * N;
            float v0 = accf[mi][ni][0], v1 = accf[mi][ni][1];
            float v2 = accf[mi][ni][2], v3 = accf[mi][ni][3];
            if (acc) {
                float2 o0 = *(float2*)p0, o1 = *(float2*)p1;
                v0 += o0.x; v1 += o0.y; v2 += o1.x; v3 += o1.y;
            }
            *(float2*)p0 = make_float2(v0, v1);
            *(float2*)p1 = make_float2(v2, v3);
        }
}
#define SMEM_S256 (2 * (SA_HALF + BK * (256 * 2 + 16)))   // 104448

// ================= bf16 hi/lo 3-pass GEMM (router only, 2-stage) =================
template<int BN_T>
__global__ __launch_bounds__(512, 1)
void hmma3_kernel(const __nv_bfloat16* __restrict__ Ah, const __nv_bfloat16* __restrict__ Al,
                  const __nv_bfloat16* __restrict__ Bh, const __nv_bfloat16* __restrict__ Bl,
                  float* __restrict__ C, int N, int Kd)
{
    constexpr int WN      = BN_T / 4;
    constexpr int NH      = BN_T / 64;
    constexpr int B_STR_T = BN_T * 2 + 16;
    constexpr int SB_HALF = BK * B_STR_T;
    constexpr int STAGEB  = 2 * SA_HALF + 2 * SB_HALF;
    constexpr int NBCH    = BN_T / 8;
    constexpr int B_ITERS = (BK * NBCH) / 512;

    extern __shared__ char smem[];
    const uint32_t sb = smem_u32(smem);
    const int tid  = threadIdx.x;
    const int lane = tid & 31;
    const int wid  = tid >> 5;
    const int wr   = wid & 3;
    const int wc   = wid >> 2;
    const int row0 = blockIdx.x * BM;
    const int col0 = blockIdx.y * BN_T;
    const int nch  = Kd >> 6;

    float accf[2][2 * NH][4];
#pragma unroll
    for (int i = 0; i < 2; i++)
#pragma unroll
        for (int j = 0; j < 2 * NH; j++)
#pragma unroll
            for (int q = 0; q < 4; q++) accf[i][j][q] = 0.f;

    auto load_stage = [&](int stg, int k0) {
        uint32_t s0 = sb + stg * STAGEB;
#pragma unroll
        for (int it = 0; it < 2; it++) {
            int idx = it * 512 + tid;
            int r = idx >> 3, c = idx & 7;
            const __nv_bfloat16* gh = Ah + (size_t)(row0 + r) * Kd + k0 + c * 8;
            const __nv_bfloat16* gl = Al + (size_t)(row0 + r) * Kd + k0 + c * 8;
            uint32_t d = s0 + r * A_STR + c * 16;
            cp16(d, gh);
            cp16(d + SA_HALF, gl);
        }
#pragma unroll
        for (int it = 0; it < B_ITERS; it++) {
            int idx = it * 512 + tid;
            int r = idx / NBCH, c = idx % NBCH;
            const __nv_bfloat16* gh = Bh + (size_t)(k0 + r) * N + col0 + c * 8;
            const __nv_bfloat16* gl = Bl + (size_t)(k0 + r) * N + col0 + c * 8;
            uint32_t d = s0 + 2 * SA_HALF + r * B_STR_T + c * 16;
            cp16(d, gh);
            cp16(d + SB_HALF, gl);
        }
        cp_commit();
    };

    load_stage(0, 0);

    const int a_row  = wr * 32 + (lane & 15);
    const int a_colb = (lane >> 4) << 4;
    const int b_row  = lane & 15;
    const int b_colb = (wc * WN + ((lane >> 4) << 3)) * 2;

    for (int ch = 0; ch < nch; ch++) {
        cp_wait<0>();
        __syncthreads();
        if (ch + 1 < nch) load_stage((ch + 1) & 1, (ch + 1) << 6);

        uint32_t sA = sb + (ch & 1) * STAGEB;
        uint32_t sB = sA + 2 * SA_HALF;

#pragma unroll
        for (int ks = 0; ks < 4; ks++) {
            const int k16 = ks << 4;
            uint32_t Ahf[2][4], Alf[2][4];
#pragma unroll
            for (int mi = 0; mi < 2; mi++) {
                uint32_t ad = sA + (a_row + mi * 16) * A_STR + k16 * 2 + a_colb;
                ldsm4(Ahf[mi], ad);
                ldsm4(Alf[mi], ad + SA_HALF);
            }
#pragma unroll
            for (int nh = 0; nh < NH; nh++) {
                uint32_t Bhf[4], Blf[4];
                uint32_t bd = sB + (b_row + k16) * B_STR_T + b_colb + nh * 32;
                ldsm4t(Bhf, bd);
                ldsm4t(Blf, bd + SB_HALF);
#pragma unroll
                for (int mi = 0; mi < 2; mi++)
#pragma unroll
                    for (int q = 0; q < 2; q++) {
                        float* d = accf[mi][nh * 2 + q];
                        mma_bf16(d, Ahf[mi], Bhf[q * 2], Bhf[q * 2 + 1]);
                        mma_bf16(d, Alf[mi], Bhf[q * 2], Bhf[q * 2 + 1]);
                        mma_bf16(d, Ahf[mi], Blf[q * 2], Blf[q * 2 + 1]);
                    }
            }
        }
    }

    const int er = row0 + wr * 32 + (lane >> 2);
    const int ec = col0 + wc * WN + (lane & 3) * 2;
#pragma unroll
    for (int mi = 0; mi < 2; mi++)
#pragma unroll
        for (int ni = 0; ni < 2 * NH; ni++) {
            float* p0 = C + (size_t)(er + mi * 16) * N + ec + ni * 8;
            float* p1 = p0 + 8 * N;
            *(float2*)p0 = make_float2(accf[mi][ni][0], accf[mi][ni][1]);
            *(float2*)p1 = make_float2(accf[mi][ni][2], accf[mi][ni][3]);
        }
}
#define SMEM_128 (2 * (2 * SA_HALF + 2 * (BK * (128 * 2 + 16))))

// ================= conversions =================
__global__ void convx_kernel(const float4* __restrict__ src, __half* __restrict__ xh,
                             __nv_bfloat16* __restrict__ bh, __nv_bfloat16* __restrict__ bl, int n4)
{
    int i = blockIdx.x * 256 + threadIdx.x;
    if (i >= n4) return;
    float4 v = src[i];
    __half2* dp = (__half2*)(xh + i * 4);
    dp[0] = __floats2half2_rn(v.x, v.y);
    dp[1] = __floats2half2_rn(v.z, v.w);
    __nv_bfloat16 h0 = __float2bfloat16_rn(v.x), h1 = __float2bfloat16_rn(v.y);
    __nv_bfloat16 h2 = __float2bfloat16_rn(v.z), h3 = __float2bfloat16_rn(v.w);
    __nv_bfloat162 hh0 = {h0, h1}, hh1 = {h2, h3};
    __nv_bfloat162 ll0 = {__float2bfloat16_rn(v.x - __bfloat162float(h0)),
                          __float2bfloat16_rn(v.y - __bfloat162float(h1))};
    __nv_bfloat162 ll1 = {__float2bfloat16_rn(v.z - __bfloat162float(h2)),
                          __float2bfloat16_rn(v.w - __bfloat162float(h3))};
    *(__nv_bfloat162*)(bh + i * 4)     = hh0;
    *(__nv_bfloat162*)(bh + i * 4 + 2) = hh1;
    *(__nv_bfloat162*)(bl + i * 4)     = ll0;
    *(__nv_bfloat162*)(bl + i * 4 + 2) = ll1;
}

__global__ void conv1_kernel(const float4* __restrict__ src, __half* __restrict__ dst, int n4)
{
    int i = blockIdx.x * 256 + threadIdx.x;
    if (i >= n4) return;
    float4 v = src[i];
    __half2* dp = (__half2*)(dst + i * 4);
    dp[0] = __floats2half2_rn(v.x, v.y);
    dp[1] = __floats2half2_rn(v.z, v.w);
}

__global__ void split_kernel(const float4* __restrict__ src,
                             __nv_bfloat16* __restrict__ hi,
                             __nv_bfloat16* __restrict__ lo, int n4)
{
    int i = blockIdx.x * 256 + threadIdx.x;
    if (i >= n4) return;
    float4 v = src[i];
    __nv_bfloat16 h0 = __float2bfloat16_rn(v.x), h1 = __float2bfloat16_rn(v.y);
    __nv_bfloat16 h2 = __float2bfloat16_rn(v.z), h3 = __float2bfloat16_rn(v.w);
    __nv_bfloat162 hh0 = {h0, h1}, hh1 = {h2, h3};
    __nv_bfloat162 ll0 = {__float2bfloat16_rn(v.x - __bfloat162float(h0)),
                          __float2bfloat16_rn(v.y - __bfloat162float(h1))};
    __nv_bfloat162 ll1 = {__float2bfloat16_rn(v.z - __bfloat162float(h2)),
                          __float2bfloat16_rn(v.w - __bfloat162float(h3))};
    *(__nv_bfloat162*)(hi + i * 4)     = hh0;
    *(__nv_bfloat162*)(hi + i * 4 + 2) = hh1;
    *(__nv_bfloat162*)(lo + i * 4)     = ll0;
    *(__nv_bfloat162*)(lo + i * 4 + 2) = ll1;
}

// ================= amplitudes -> normalized mix =================
__global__ void mix_kernel(const float* __restrict__ amp)
{
    int e = threadIdx.x;
    if (e >= NE) return;
    float p[KQ];
    float s = 0.f;
#pragma unroll
    for (int k = 0; k < KQ; k++) {
        float a0 = amp[(e * KQ + k) * 2 + 0];
        float a1 = amp[(e * KQ + k) * 2 + 1];
        p[k] = a0 * a0 + a1 * a1;
        s += p[k];
    }
    float inv = 1.f / (s + 1e-8f);
#pragma unroll
    for (int k = 0; k < KQ; k++) g_mix[e * KQ + k] = p[k] * inv;
}

// ================= softmax + top-4 + collapse =================
__global__ void topk_kernel(const float* __restrict__ expert_scale)
{
    int lane = threadIdx.x & 31;
    int warp = threadIdx.x >> 5;
    int t = blockIdx.x * 8 + warp;
    const float* lrow = g_logits + (size_t)t * NE;

    float v[4];
#pragma unroll
    for (int j = 0; j < 4; j++) v[j] = lrow[lane + 32 * j];

    float m = fmaxf(fmaxf(v[0], v[1]), fmaxf(v[2], v[3]));
#pragma unroll
    for (int o = 16; o; o >>= 1) m = fmaxf(m, __shfl_xor_sync(0xffffffffu, m, o));

    float D = 0.f;
#pragma unroll
    for (int j = 0; j < 4; j++) D += expf(v[j] - m);
#pragma unroll
    for (int o = 16; o; o >>= 1) D += __shfl_xor_sync(0xffffffffu, D, o);

    float lv[4] = {v[0], v[1], v[2], v[3]};
    float selv[4];
    int   seli[4];
#pragma unroll
    for (int it = 0; it < 4; it++) {
        float bv = -FLT_MAX;
        int   bi = NE;
#pragma unroll
        for (int j = 0; j < 4; j++) {
            int e = lane + 32 * j;
            if (lv[j] > bv) { bv = lv[j]; bi = e; }
        }
#pragma unroll
        for (int o = 16; o; o >>= 1) {
            float ov = __shfl_xor_sync(0xffffffffu, bv, o);
            int   oi = __shfl_xor_sync(0xffffffffu, bi, o);
            if (ov > bv || (ov == bv && oi < bi)) { bv = ov; bi = oi; }
        }
        selv[it] = bv;
        seli[it] = bi;
        if ((bi & 31) == lane) lv[bi >> 5] = -FLT_MAX;
    }

    float ew[4];
    float S = 0.f;
#pragma unroll
    for (int it = 0; it < 4; it++) { ew[it] = expf(selv[it] - m); S += ew[it]; }
    float denom = S + 1e-8f * D;

    if (lane < KQ) {
        float acc = 0.f;
#pragma unroll
        for (int it = 0; it < 4; it++)
            acc += (ew[it] / denom) * expert_scale[seli[it]] * g_mix[seli[it] * KQ + lane];
        g_wk[t * KQ + lane] = acc;
    }
}

// ================= z = sum_k wk * p[t,k,i]  (fp16 in, fp16 out) =================
__global__ void moe_mix_kernel()
{
    int t = blockIdx.y;
    int i = (blockIdx.x * 256 + threadIdx.x) * 2;
    __shared__ float w[KQ];
    if (threadIdx.x < KQ) w[threadIdx.x] = g_wk[t * KQ + threadIdx.x];
    __syncthreads();
    float a0 = 0.f, a1 = 0.f;
#pragma unroll
    for (int k = 0; k < KQ; k++) {
        __half2 p2 = *(const __half2*)(h_p + (size_t)t * KI + k * ID + i);
        a0 += w[k] * __low2float(p2);
        a1 += w[k] * __high2float(p2);
    }
    *(__half2*)(h_z + (size_t)t * ID + i) = __floats2half2_rn(a0, a1);
}

// ================= host side =================
static void gemm1f(const void* A, const void* B, float* C, int M, int N, int Kd, int acc)
{
    dim3 grid(M / BM, N / 256);
    hmma1f_kernel<256><<<grid, 512, SMEM_S256>>>(
        (const __half*)A, (const __half*)B, C, N, Kd, acc);
}

extern "C" void kernel_launch(void* const* d_in, const int* in_sizes, int n_in,
                              void* d_out, int out_size)
{
    const float* x             = (const float*)d_in[0];
    const float* w_router      = (const float*)d_in[1];
    const float* w_gate        = (const float*)d_in[2];
    const float* w_up          = (const float*)d_in[3];
    const float* w_down        = (const float*)d_in[4];
    const float* amplitudes    = (const float*)d_in[5];
    const float* expert_scale  = (const float*)d_in[6];
    const float* shared_w_gate = (const float*)d_in[7];
    const float* shared_w_up   = (const float*)d_in[8];
    const float* shared_w_down = (const float*)d_in[9];
    float* out = (float*)d_out;

    cudaFuncSetAttribute(hmma_gu_kernel, cudaFuncAttributeMaxDynamicSharedMemorySize, SMEM_GU);
    cudaFuncSetAttribute(hmma1f_kernel<256>, cudaFuncAttributeMaxDynamicSharedMemorySize, SMEM_S256);
    cudaFuncSetAttribute(hmma3_kernel<128>, cudaFuncAttributeMaxDynamicSharedMemorySize, SMEM_128);

    void *px, *pwg, *pwu, *pwd, *psgw, *psuw, *psdw;
    void *pp, *pz, *ph, *plog;
    void *bxh, *bxl, *bwrh, *bwrl;
    cudaGetSymbolAddress(&px, h_x);
    cudaGetSymbolAddress(&pwg, h_wg);   cudaGetSymbolAddress(&pwu, h_wu);
    cudaGetSymbolAddress(&pwd, h_wd);
    cudaGetSymbolAddress(&psgw, h_sgw); cudaGetSymbolAddress(&psuw, h_suw);
    cudaGetSymbolAddress(&psdw, h_sdw);
    cudaGetSymbolAddress(&pp, h_p);
    cudaGetSymbolAddress(&pz, h_z);     cudaGetSymbolAddress(&ph, h_h);
    cudaGetSymbolAddress(&plog, g_logits);
    cudaGetSymbolAddress(&bxh, g_xh);   cudaGetSymbolAddress(&bxl, g_xl);
    cudaGetSymbolAddress(&bwrh, g_wrh); cudaGetSymbolAddress(&bwrl, g_wrl);

    // 1. conversions (x read once -> fp16 + bf16 limbs)
    convx_kernel<<<(T_TOK * HD / 4) / 256, 256>>>((const float4*)x, (__half*)px,
                                                  (__nv_bfloat16*)bxh, (__nv_bfloat16*)bxl, T_TOK * HD / 4);
    conv1_kernel<<<(HD * KI / 4) / 256, 256>>>((const float4*)w_gate, (__half*)pwg, HD * KI / 4);
    conv1_kernel<<<(HD * KI / 4) / 256, 256>>>((const float4*)w_up,   (__half*)pwu, HD * KI / 4);
    conv1_kernel<<<(ID * HD / 4) / 256, 256>>>((const float4*)w_down, (__half*)pwd, ID * HD / 4);
    conv1_kernel<<<(HD * I2 / 4) / 256, 256>>>((const float4*)shared_w_gate, (__half*)psgw, HD * I2 / 4);
    conv1_kernel<<<(HD * I2 / 4) / 256, 256>>>((const float4*)shared_w_up,   (__half*)psuw, HD * I2 / 4);
    conv1_kernel<<<(I2 * HD / 4) / 256, 256>>>((const float4*)shared_w_down, (__half*)psdw, I2 * HD / 4);
    split_kernel<<<(HD * NE / 4) / 256, 256>>>((const float4*)w_router, (__nv_bfloat16*)bwrh, (__nv_bfloat16*)bwrl, HD * NE / 4);

    // 2. router path in bf16x3 (precision-sensitive: top-k selection)
    mix_kernel<<<1, 128>>>(amplitudes);
    hmma3_kernel<128><<<dim3(T_TOK / BM, 1), 512, SMEM_128>>>(
        (const __nv_bfloat16*)bxh, (const __nv_bfloat16*)bxl,
        (const __nv_bfloat16*)bwrh, (const __nv_bfloat16*)bwrl, (float*)plog, NE, HD);
    topk_kernel<<<T_TOK / 8, 256>>>(expert_scale);

    // 3. fused gate/up GEMM + silu: p = silu(x@Wg) * (x@Wu)
    hmma_gu_kernel<<<dim3(T_TOK / BM, KI / 128), 512, SMEM_GU>>>(
        (const __half*)px, (const __half*)pwg, (const __half*)pwu, (__half*)pp, KI, HD);

    // 4. z = sum_k wk * p -> fp16
    moe_mix_kernel<<<dim3(ID / 512, T_TOK), 256>>>();

    // 5. down projection: out = z @ w_down
    gemm1f(pz, pwd, out, T_TOK, HD, ID, 0);

    // 6. fused shared expert: h = silu(x@Wg_s) * (x@Wu_s)
    hmma_gu_kernel<<<dim3(T_TOK / BM, I2 / 128), 512, SMEM_GU>>>(
        (const __half*)px, (const __half*)psgw, (const __half*)psuw, (__half*)ph, I2, HD);

    // 7. out += h @ shared_w_down
    gemm1f(ph, psdw, out, T_TOK, HD, I2, 1);
}

// round 16
// speedup vs baseline: 1.0435x; 1.0209x over previous
#include <cuda_runtime.h>
#include <cuda_bf16.h>
#include <cuda_fp16.h>
#include <math.h>
#include <float.h>
#include <stdint.h>

// ---------------- problem constants ----------------
#define T_TOK 8192
#define HD    2048
#define ID    1024
#define KQ    8
#define NE    128
#define KI    8192
#define I2    2048
#define KC    3072        // ID + I2 combined down-proj K

// ---------------- fp32 scratch ----------------
__device__ float g_logits[1048576];  // [T, NE]
__device__ float g_wk[65536];        // [T, KQ]
__device__ float g_mix[1024];        // [NE, KQ]

// ---------------- fp16 scratch ----------------
__device__ __half h_x[16777216];                    // x [T,HD]
__device__ __half h_wg[16777216];                   // w_gate [HD,KI]
__device__ __half h_wu[16777216];                   // w_up
__device__ __half h_sgw[4194304];                   // shared_w_gate [HD,I2]
__device__ __half h_suw[4194304];                   // shared_w_up
__device__ __half h_wc[6291456];                    // [w_down ; shared_w_down] [KC,HD]
__device__ __half h_p[67108864];                    // silu(gate)*up [T,KI]
__device__ __half h_zc[25165824];                   // [z | h] [T,KC]

// bf16 (router only)
__device__ __nv_bfloat16 g_xh[16777216], g_xl[16777216];
__device__ __nv_bfloat16 g_wrh[262144],  g_wrl[262144];

// ================= low-level helpers =================
__device__ __forceinline__ uint32_t smem_u32(const void* p) {
    uint32_t a;
    asm("{ .reg .u64 t; cvta.to.shared.u64 t, %1; cvt.u32.u64 %0, t; }" : "=r"(a) : "l"(p));
    return a;
}
__device__ __forceinline__ void cp16(uint32_t dst, const void* src) {
    asm volatile("cp.async.cg.shared.global [%0], [%1], 16;" :: "r"(dst), "l"(src));
}
__device__ __forceinline__ void cp_commit() {
    asm volatile("cp.async.commit_group;" ::: "memory");
}
template<int N> __device__ __forceinline__ void cp_wait() {
    asm volatile("cp.async.wait_group %0;" :: "n"(N) : "memory");
}
__device__ __forceinline__ void ldsm4(uint32_t* r, uint32_t addr) {
    asm volatile("ldmatrix.sync.aligned.m8n8.x4.shared.b16 {%0,%1,%2,%3}, [%4];"
                 : "=r"(r[0]), "=r"(r[1]), "=r"(r[2]), "=r"(r[3]) : "r"(addr));
}
__device__ __forceinline__ void ldsm4t(uint32_t* r, uint32_t addr) {
    asm volatile("ldmatrix.sync.aligned.m8n8.x4.trans.shared.b16 {%0,%1,%2,%3}, [%4];"
                 : "=r"(r[0]), "=r"(r[1]), "=r"(r[2]), "=r"(r[3]) : "r"(addr));
}
__device__ __forceinline__ void mma_bf16(float* d, const uint32_t* a, uint32_t b0, uint32_t b1) {
    asm volatile("mma.sync.aligned.m16n8k16.row.col.f32.bf16.bf16.f32 "
                 "{%0,%1,%2,%3}, {%4,%5,%6,%7}, {%8,%9}, {%0,%1,%2,%3};"
                 : "+f"(d[0]), "+f"(d[1]), "+f"(d[2]), "+f"(d[3])
                 : "r"(a[0]), "r"(a[1]), "r"(a[2]), "r"(a[3]), "r"(b0), "r"(b1));
}
__device__ __forceinline__ void mma_f16(float* d, const uint32_t* a, uint32_t b0, uint32_t b1) {
    asm volatile("mma.sync.aligned.m16n8k16.row.col.f32.f16.f16.f32 "
                 "{%0,%1,%2,%3}, {%4,%5,%6,%7}, {%8,%9}, {%0,%1,%2,%3};"
                 : "+f"(d[0]), "+f"(d[1]), "+f"(d[2]), "+f"(d[3])
                 : "r"(a[0]), "r"(a[1]), "r"(a[2]), "r"(a[3]), "r"(b0), "r"(b1));
}

__device__ __forceinline__ float silu_mul(float g, float u) {
    return (g / (1.f + expf(-g))) * u;
}

#define BM 128
#define BK 64
#define A_STR 144
#define SA_HALF (BM * A_STR)

// ================= fused dual-B GEMM: P = silu(A@Bg) * (A@Bu), fp16 out =================
// A [M,Kd], Bg/Bu [Kd,NB], P row stride NP, P pre-offset by caller.
#define GB_STR 272
#define GSB (BK * GB_STR)
#define GSTAGE (SA_HALF + 2 * GSB)
#define SMEM_GU (2 * GSTAGE)

__global__ __launch_bounds__(512, 1)
void hmma_gu_kernel(const __half* __restrict__ A, const __half* __restrict__ Bg,
                    const __half* __restrict__ Bu, __half* __restrict__ P,
                    int NB, int NP, int Kd)
{
    extern __shared__ char smem[];
    const uint32_t sb = smem_u32(smem);
    const int tid  = threadIdx.x;
    const int lane = tid & 31;
    const int wid  = tid >> 5;
    const int wr   = wid & 3;
    const int wc   = wid >> 2;
    const int row0 = blockIdx.x * BM;
    const int col0 = blockIdx.y * 128;
    const int nch  = Kd >> 6;

    float accg[2][4][4], accu[2][4][4];
#pragma unroll
    for (int i = 0; i < 2; i++)
#pragma unroll
        for (int j = 0; j < 4; j++)
#pragma unroll
            for (int q = 0; q < 4; q++) { accg[i][j][q] = 0.f; accu[i][j][q] = 0.f; }

    auto load_stage = [&](int stg, int k0) {
        uint32_t s0 = sb + stg * GSTAGE;
#pragma unroll
        for (int it = 0; it < 2; it++) {
            int idx = it * 512 + tid;
            int r = idx >> 3, c = idx & 7;
            cp16(s0 + r * A_STR + c * 16, A + (size_t)(row0 + r) * Kd + k0 + c * 8);
        }
#pragma unroll
        for (int it = 0; it < 2; it++) {
            int idx = it * 512 + tid;
            int r = idx >> 4, c = idx & 15;
            size_t go = (size_t)(k0 + r) * NB + col0 + c * 8;
            uint32_t d = s0 + SA_HALF + r * GB_STR + c * 16;
            cp16(d, Bg + go);
            cp16(d + GSB, Bu + go);
        }
        cp_commit();
    };

    load_stage(0, 0);

    const int a_row  = wr * 32 + (lane & 15);
    const int a_colb = (lane >> 4) << 4;
    const int b_row  = lane & 15;
    const int b_colb = (wc * 32 + ((lane >> 4) << 3)) * 2;

    for (int ch = 0; ch < nch; ch++) {
        cp_wait<0>();
        __syncthreads();
        if (ch + 1 < nch) load_stage((ch + 1) & 1, (ch + 1) << 6);

        uint32_t sA  = sb + (ch & 1) * GSTAGE;
        uint32_t sBg = sA + SA_HALF;
        uint32_t sBu = sBg + GSB;

#pragma unroll
        for (int ks = 0; ks < 4; ks++) {
            const int k16 = ks << 4;
            uint32_t Af[2][4];
#pragma unroll
            for (int mi = 0; mi < 2; mi++)
                ldsm4(Af[mi], sA + (a_row + mi * 16) * A_STR + k16 * 2 + a_colb);
#pragma unroll
            for (int nh = 0; nh < 2; nh++) {
                uint32_t Bgf[4], Buf[4];
                uint32_t bo = (b_row + k16) * GB_STR + b_colb + nh * 32;
                ldsm4t(Bgf, sBg + bo);
                ldsm4t(Buf, sBu + bo);
#pragma unroll
                for (int mi = 0; mi < 2; mi++)
#pragma unroll
                    for (int q = 0; q < 2; q++) {
                        mma_f16(accg[mi][nh * 2 + q], Af[mi], Bgf[q * 2], Bgf[q * 2 + 1]);
                        mma_f16(accu[mi][nh * 2 + q], Af[mi], Buf[q * 2], Buf[q * 2 + 1]);
                    }
            }
        }
    }

    const int er = row0 + wr * 32 + (lane >> 2);
    const int ec = col0 + wc * 32 + (lane & 3) * 2;
#pragma unroll
    for (int mi = 0; mi < 2; mi++)
#pragma unroll
        for (int ni = 0; ni < 4; ni++) {
            __half* p0 = P + (size_t)(er + mi * 16) * NP + ec + ni * 8;
            __half* p1 = p0 + 8 * NP;
            *(__half2*)p0 = __floats2half2_rn(silu_mul(accg[mi][ni][0], accu[mi][ni][0]),
                                              silu_mul(accg[mi][ni][1], accu[mi][ni][1]));
            *(__half2*)p1 = __floats2half2_rn(silu_mul(accg[mi][ni][2], accu[mi][ni][2]),
                                              silu_mul(accg[mi][ni][3], accu[mi][ni][3]));
        }
}

// ================= fp16 single-pass GEMM, fp32 output, 2-stage =================
template<int BN_T>
__global__ __launch_bounds__(512, 1)
void hmma1f_kernel(const __half* __restrict__ A, const __half* __restrict__ B,
                   float* __restrict__ C, int N, int Kd)
{
    constexpr int WN      = BN_T / 4;
    constexpr int NH      = BN_T / 64;
    constexpr int B_STR_T = BN_T * 2 + 16;
    constexpr int SB      = BK * B_STR_T;
    constexpr int STAGEB  = SA_HALF + SB;
    constexpr int NBCH    = BN_T / 8;
    constexpr int B_ITERS = (BK * NBCH) / 512;

    extern __shared__ char smem[];
    const uint32_t sb = smem_u32(smem);
    const int tid  = threadIdx.x;
    const int lane = tid & 31;
    const int wid  = tid >> 5;
    const int wr   = wid & 3;
    const int wc   = wid >> 2;
    const int row0 = blockIdx.x * BM;
    const int col0 = blockIdx.y * BN_T;
    const int nch  = Kd >> 6;

    float accf[2][2 * NH][4];
#pragma unroll
    for (int i = 0; i < 2; i++)
#pragma unroll
        for (int j = 0; j < 2 * NH; j++)
#pragma unroll
            for (int q = 0; q < 4; q++) accf[i][j][q] = 0.f;

    auto load_stage = [&](int stg, int k0) {
        uint32_t s0 = sb + stg * STAGEB;
#pragma unroll
        for (int it = 0; it < 2; it++) {
            int idx = it * 512 + tid;
            int r = idx >> 3, c = idx & 7;
            cp16(s0 + r * A_STR + c * 16, A + (size_t)(row0 + r) * Kd + k0 + c * 8);
        }
#pragma unroll
        for (int it = 0; it < B_ITERS; it++) {
            int idx = it * 512 + tid;
            int r = idx / NBCH, c = idx % NBCH;
            cp16(s0 + SA_HALF + r * B_STR_T + c * 16, B + (size_t)(k0 + r) * N + col0 + c * 8);
        }
        cp_commit();
    };

    load_stage(0, 0);

    const int a_row  = wr * 32 + (lane & 15);
    const int a_colb = (lane >> 4) << 4;
    const int b_row  = lane & 15;
    const int b_colb = (wc * WN + ((lane >> 4) << 3)) * 2;

    for (int ch = 0; ch < nch; ch++) {
        cp_wait<0>();
        __syncthreads();
        if (ch + 1 < nch) load_stage((ch + 1) & 1, (ch + 1) << 6);

        uint32_t sA = sb + (ch & 1) * STAGEB;
        uint32_t sB = sA + SA_HALF;

#pragma unroll
        for (int ks = 0; ks < 4; ks++) {
            const int k16 = ks << 4;
            uint32_t Af[2][4];
#pragma unroll
            for (int mi = 0; mi < 2; mi++)
                ldsm4(Af[mi], sA + (a_row + mi * 16) * A_STR + k16 * 2 + a_colb);
#pragma unroll
            for (int nh = 0; nh < NH; nh++) {
                uint32_t Bf[4];
                ldsm4t(Bf, sB + (b_row + k16) * B_STR_T + b_colb + nh * 32);
#pragma unroll
                for (int mi = 0; mi < 2; mi++)
#pragma unroll
                    for (int q = 0; q < 2; q++)
                        mma_f16(accf[mi][nh * 2 + q], Af[mi], Bf[q * 2], Bf[q * 2 + 1]);
            }
        }
    }

    const int er = row0 + wr * 32 + (lane >> 2);
    const int ec = col0 + wc * WN + (lane & 3) * 2;
#pragma unroll
    for (int mi = 0; mi < 2; mi++)
#pragma unroll
        for (int ni = 0; ni < 2 * NH; ni++) {
            float* p0 = C + (size_t)(er + mi * 16) * N + ec + ni * 8;
            float* p1 = p0 + 8 * N;
            *(float2*)p0 = make_float2(accf[mi][ni][0], accf[mi][ni][1]);
            *(float2*)p1 = make_float2(accf[mi][ni][2], accf[mi][ni][3]);
        }
}
#define SMEM_S256 (2 * (SA_HALF + BK * (256 * 2 + 16)))   // 104448

// ================= bf16 hi/lo 3-pass GEMM (router only, 2-stage) =================
template<int BN_T>
__global__ __launch_bounds__(512, 1)
void hmma3_kernel(const __nv_bfloat16* __restrict__ Ah, const __nv_bfloat16* __restrict__ Al,
                  const __nv_bfloat16* __restrict__ Bh, const __nv_bfloat16* __restrict__ Bl,
                  float* __restrict__ C, int N, int Kd)
{
    constexpr int WN      = BN_T / 4;
    constexpr int NH      = BN_T / 64;
    constexpr int B_STR_T = BN_T * 2 + 16;
    constexpr int SB_HALF = BK * B_STR_T;
    constexpr int STAGEB  = 2 * SA_HALF + 2 * SB_HALF;
    constexpr int NBCH    = BN_T / 8;
    constexpr int B_ITERS = (BK * NBCH) / 512;

    extern __shared__ char smem[];
    const uint32_t sb = smem_u32(smem);
    const int tid  = threadIdx.x;
    const int lane = tid & 31;
    const int wid  = tid >> 5;
    const int wr   = wid & 3;
    const int wc   = wid >> 2;
    const int row0 = blockIdx.x * BM;
    const int col0 = blockIdx.y * BN_T;
    const int nch  = Kd >> 6;

    float accf[2][2 * NH][4];
#pragma unroll
    for (int i = 0; i < 2; i++)
#pragma unroll
        for (int j = 0; j < 2 * NH; j++)
#pragma unroll
            for (int q = 0; q < 4; q++) accf[i][j][q] = 0.f;

    auto load_stage = [&](int stg, int k0) {
        uint32_t s0 = sb + stg * STAGEB;
#pragma unroll
        for (int it = 0; it < 2; it++) {
            int idx = it * 512 + tid;
            int r = idx >> 3, c = idx & 7;
            const __nv_bfloat16* gh = Ah + (size_t)(row0 + r) * Kd + k0 + c * 8;
            const __nv_bfloat16* gl = Al + (size_t)(row0 + r) * Kd + k0 + c * 8;
            uint32_t d = s0 + r * A_STR + c * 16;
            cp16(d, gh);
            cp16(d + SA_HALF, gl);
        }
#pragma unroll
        for (int it = 0; it < B_ITERS; it++) {
            int idx = it * 512 + tid;
            int r = idx / NBCH, c = idx % NBCH;
            const __nv_bfloat16* gh = Bh + (size_t)(k0 + r) * N + col0 + c * 8;
            const __nv_bfloat16* gl = Bl + (size_t)(k0 + r) * N + col0 + c * 8;
            uint32_t d = s0 + 2 * SA_HALF + r * B_STR_T + c * 16;
            cp16(d, gh);
            cp16(d + SB_HALF, gl);
        }
        cp_commit();
    };

    load_stage(0, 0);

    const int a_row  = wr * 32 + (lane & 15);
    const int a_colb = (lane >> 4) << 4;
    const int b_row  = lane & 15;
    const int b_colb = (wc * WN + ((lane >> 4) << 3)) * 2;

    for (int ch = 0; ch < nch; ch++) {
        cp_wait<0>();
        __syncthreads();
        if (ch + 1 < nch) load_stage((ch + 1) & 1, (ch + 1) << 6);

        uint32_t sA = sb + (ch & 1) * STAGEB;
        uint32_t sB = sA + 2 * SA_HALF;

#pragma unroll
        for (int ks = 0; ks < 4; ks++) {
            const int k16 = ks << 4;
            uint32_t Ahf[2][4], Alf[2][4];
#pragma unroll
            for (int mi = 0; mi < 2; mi++) {
                uint32_t ad = sA + (a_row + mi * 16) * A_STR + k16 * 2 + a_colb;
                ldsm4(Ahf[mi], ad);
                ldsm4(Alf[mi], ad + SA_HALF);
            }
#pragma unroll
            for (int nh = 0; nh < NH; nh++) {
                uint32_t Bhf[4], Blf[4];
                uint32_t bd = sB + (b_row + k16) * B_STR_T + b_colb + nh * 32;
                ldsm4t(Bhf, bd);
                ldsm4t(Blf, bd + SB_HALF);
#pragma unroll
                for (int mi = 0; mi < 2; mi++)
#pragma unroll
                    for (int q = 0; q < 2; q++) {
                        float* d = accf[mi][nh * 2 + q];
                        mma_bf16(d, Ahf[mi], Bhf[q * 2], Bhf[q * 2 + 1]);
                        mma_bf16(d, Alf[mi], Bhf[q * 2], Bhf[q * 2 + 1]);
                        mma_bf16(d, Ahf[mi], Blf[q * 2], Blf[q * 2 + 1]);
                    }
            }
        }
    }

    const int er = row0 + wr * 32 + (lane >> 2);
    const int ec = col0 + wc * WN + (lane & 3) * 2;
#pragma unroll
    for (int mi = 0; mi < 2; mi++)
#pragma unroll
        for (int ni = 0; ni < 2 * NH; ni++) {
            float* p0 = C + (size_t)(er + mi * 16) * N + ec + ni * 8;
            float* p1 = p0 + 8 * N;
            *(float2*)p0 = make_float2(accf[mi][ni][0], accf[mi][ni][1]);
            *(float2*)p1 = make_float2(accf[mi][ni][2], accf[mi][ni][3]);
        }
}
#define SMEM_128 (2 * (2 * SA_HALF + 2 * (BK * (128 * 2 + 16))))

// ================= conversions =================
__global__ void convx_kernel(const float4* __restrict__ src, __half* __restrict__ xh,
                             __nv_bfloat16* __restrict__ bh, __nv_bfloat16* __restrict__ bl, int n4)
{
    int i = blockIdx.x * 256 + threadIdx.x;
    if (i >= n4) return;
    float4 v = src[i];
    __half2* dp = (__half2*)(xh + i * 4);
    dp[0] = __floats2half2_rn(v.x, v.y);
    dp[1] = __floats2half2_rn(v.z, v.w);
    __nv_bfloat16 h0 = __float2bfloat16_rn(v.x), h1 = __float2bfloat16_rn(v.y);
    __nv_bfloat16 h2 = __float2bfloat16_rn(v.z), h3 = __float2bfloat16_rn(v.w);
    __nv_bfloat162 hh0 = {h0, h1}, hh1 = {h2, h3};
    __nv_bfloat162 ll0 = {__float2bfloat16_rn(v.x - __bfloat162float(h0)),
                          __float2bfloat16_rn(v.y - __bfloat162float(h1))};
    __nv_bfloat162 ll1 = {__float2bfloat16_rn(v.z - __bfloat162float(h2)),
                          __float2bfloat16_rn(v.w - __bfloat162float(h3))};
    *(__nv_bfloat162*)(bh + i * 4)     = hh0;
    *(__nv_bfloat162*)(bh + i * 4 + 2) = hh1;
    *(__nv_bfloat162*)(bl + i * 4)     = ll0;
    *(__nv_bfloat162*)(bl + i * 4 + 2) = ll1;
}

// one launch converts all six weight tensors; segment table passed BY VALUE
// (graph-capture safe). Segment sizes are compile-time constants.
#define N4_BIG   (HD * KI / 4)     // 4M  : w_gate, w_up
#define N4_SMALL (HD * I2 / 4)     // 1M  : w_down, sgw, suw, sdw
#define BLK_BIG   (N4_BIG / 256)   // 16384
#define BLK_SMALL (N4_SMALL / 256) // 4096

__global__ void convall_kernel(const float4* s0, __half* d0,   // w_gate
                               const float4* s1, __half* d1,   // w_up
                               const float4* s2, __half* d2,   // w_down   (n4 = N4_SMALL/2)
                               const float4* s3, __half* d3,   // sgw
                               const float4* s4, __half* d4,   // suw
                               const float4* s5, __half* d5)   // sdw
{
    int b = blockIdx.x;
    const float4* src;
    __half* dst;
    int i;
    if (b < BLK_BIG)                        { src = s0; dst = d0; i = b * 256 + threadIdx.x; }
    else if (b < 2 * BLK_BIG)               { src = s1; dst = d1; i = (b - 2 * BLK_BIG + BLK_BIG) * 256 + threadIdx.x; }
    else if (b < 2 * BLK_BIG + BLK_SMALL/2) { src = s2; dst = d2; i = (b - 2 * BLK_BIG) * 256 + threadIdx.x; }
    else if (b < 2 * BLK_BIG + BLK_SMALL/2 + BLK_SMALL) { src = s3; dst = d3; i = (b - 2 * BLK_BIG - BLK_SMALL/2) * 256 + threadIdx.x; }
    else if (b < 2 * BLK_BIG + BLK_SMALL/2 + 2 * BLK_SMALL) { src = s4; dst = d4; i = (b - 2 * BLK_BIG - BLK_SMALL/2 - BLK_SMALL) * 256 + threadIdx.x; }
    else                                    { src = s5; dst = d5; i = (b - 2 * BLK_BIG - BLK_SMALL/2 - 2 * BLK_SMALL) * 256 + threadIdx.x; }
    float4 v = src[i];
    __half2* dp = (__half2*)(dst + (size_t)i * 4);
    dp[0] = __floats2half2_rn(v.x, v.y);
    dp[1] = __floats2half2_rn(v.z, v.w);
}
#define CONV_BLOCKS (2 * BLK_BIG + BLK_SMALL/2 + 3 * BLK_SMALL)

__global__ void split_kernel(const float4* __restrict__ src,
                             __nv_bfloat16* __restrict__ hi,
                             __nv_bfloat16* __restrict__ lo, int n4)
{
    int i = blockIdx.x * 256 + threadIdx.x;
    if (i >= n4) return;
    float4 v = src[i];
    __nv_bfloat16 h0 = __float2bfloat16_rn(v.x), h1 = __float2bfloat16_rn(v.y);
    __nv_bfloat16 h2 = __float2bfloat16_rn(v.z), h3 = __float2bfloat16_rn(v.w);
    __nv_bfloat162 hh0 = {h0, h1}, hh1 = {h2, h3};
    __nv_bfloat162 ll0 = {__float2bfloat16_rn(v.x - __bfloat162float(h0)),
                          __float2bfloat16_rn(v.y - __bfloat162float(h1))};
    __nv_bfloat162 ll1 = {__float2bfloat16_rn(v.z - __bfloat162float(h2)),
                          __float2bfloat16_rn(v.w - __bfloat162float(h3))};
    *(__nv_bfloat162*)(hi + i * 4)     = hh0;
    *(__nv_bfloat162*)(hi + i * 4 + 2) = hh1;
    *(__nv_bfloat162*)(lo + i * 4)     = ll0;
    *(__nv_bfloat162*)(lo + i * 4 + 2) = ll1;
}

// ================= amplitudes -> normalized mix =================
__global__ void mix_kernel(const float* __restrict__ amp)
{
    int e = threadIdx.x;
    if (e >= NE) return;
    float p[KQ];
    float s = 0.f;
#pragma unroll
    for (int k = 0; k < KQ; k++) {
        float a0 = amp[(e * KQ + k) * 2 + 0];
        float a1 = amp[(e * KQ + k) * 2 + 1];
        p[k] = a0 * a0 + a1 * a1;
        s += p[k];
    }
    float inv = 1.f / (s + 1e-8f);
#pragma unroll
    for (int k = 0; k < KQ; k++) g_mix[e * KQ + k] = p[k] * inv;
}

// ================= softmax + top-4 + collapse =================
__global__ void topk_kernel(const float* __restrict__ expert_scale)
{
    int lane = threadIdx.x & 31;
    int warp = threadIdx.x >> 5;
    int t = blockIdx.x * 8 + warp;
    const float* lrow = g_logits + (size_t)t * NE;

    float v[4];
#pragma unroll
    for (int j = 0; j < 4; j++) v[j] = lrow[lane + 32 * j];

    float m = fmaxf(fmaxf(v[0], v[1]), fmaxf(v[2], v[3]));
#pragma unroll
    for (int o = 16; o; o >>= 1) m = fmaxf(m, __shfl_xor_sync(0xffffffffu, m, o));

    float D = 0.f;
#pragma unroll
    for (int j = 0; j < 4; j++) D += expf(v[j] - m);
#pragma unroll
    for (int o = 16; o; o >>= 1) D += __shfl_xor_sync(0xffffffffu, D, o);

    float lv[4] = {v[0], v[1], v[2], v[3]};
    float selv[4];
    int   seli[4];
#pragma unroll
    for (int it = 0; it < 4; it++) {
        float bv = -FLT_MAX;
        int   bi = NE;
#pragma unroll
        for (int j = 0; j < 4; j++) {
            int e = lane + 32 * j;
            if (lv[j] > bv) { bv = lv[j]; bi = e; }
        }
#pragma unroll
        for (int o = 16; o; o >>= 1) {
            float ov = __shfl_xor_sync(0xffffffffu, bv, o);
            int   oi = __shfl_xor_sync(0xffffffffu, bi, o);
            if (ov > bv || (ov == bv && oi < bi)) { bv = ov; bi = oi; }
        }
        selv[it] = bv;
        seli[it] = bi;
        if ((bi & 31) == lane) lv[bi >> 5] = -FLT_MAX;
    }

    float ew[4];
    float S = 0.f;
#pragma unroll
    for (int it = 0; it < 4; it++) { ew[it] = expf(selv[it] - m); S += ew[it]; }
    float denom = S + 1e-8f * D;

    if (lane < KQ) {
        float acc = 0.f;
#pragma unroll
        for (int it = 0; it < 4; it++)
            acc += (ew[it] / denom) * expert_scale[seli[it]] * g_mix[seli[it] * KQ + lane];
        g_wk[t * KQ + lane] = acc;
    }
}

// ================= z = sum_k wk * p[t,k,i]  -> cols 0..ID-1 of h_zc =================
__global__ void moe_mix_kernel()
{
    int t = blockIdx.y;
    int i = (blockIdx.x * 256 + threadIdx.x) * 2;
    __shared__ float w[KQ];
    if (threadIdx.x < KQ) w[threadIdx.x] = g_wk[t * KQ + threadIdx.x];
    __syncthreads();
    float a0 = 0.f, a1 = 0.f;
#pragma unroll
    for (int k = 0; k < KQ; k++) {
        __half2 p2 = *(const __half2*)(h_p + (size_t)t * KI + k * ID + i);
        a0 += w[k] * __low2float(p2);
        a1 += w[k] * __high2float(p2);
    }
    *(__half2*)(h_zc + (size_t)t * KC + i) = __floats2half2_rn(a0, a1);
}

// ================= host side =================
extern "C" void kernel_launch(void* const* d_in, const int* in_sizes, int n_in,
                              void* d_out, int out_size)
{
    const float* x             = (const float*)d_in[0];
    const float* w_router      = (const float*)d_in[1];
    const float* w_gate        = (const float*)d_in[2];
    const float* w_up          = (const float*)d_in[3];
    const float* w_down        = (const float*)d_in[4];
    const float* amplitudes    = (const float*)d_in[5];
    const float* expert_scale  = (const float*)d_in[6];
    const float* shared_w_gate = (const float*)d_in[7];
    const float* shared_w_up   = (const float*)d_in[8];
    const float* shared_w_down = (const float*)d_in[9];
    float* out = (float*)d_out;

    cudaFuncSetAttribute(hmma_gu_kernel, cudaFuncAttributeMaxDynamicSharedMemorySize, SMEM_GU);
    cudaFuncSetAttribute(hmma1f_kernel<256>, cudaFuncAttributeMaxDynamicSharedMemorySize, SMEM_S256);
    cudaFuncSetAttribute(hmma3_kernel<128>, cudaFuncAttributeMaxDynamicSharedMemorySize, SMEM_128);

    void *px, *pwg, *pwu, *psgw, *psuw, *pwc;
    void *pp, *pzc, *plog;
    void *bxh, *bxl, *bwrh, *bwrl;
    cudaGetSymbolAddress(&px, h_x);
    cudaGetSymbolAddress(&pwg, h_wg);   cudaGetSymbolAddress(&pwu, h_wu);
    cudaGetSymbolAddress(&psgw, h_sgw); cudaGetSymbolAddress(&psuw, h_suw);
    cudaGetSymbolAddress(&pwc, h_wc);
    cudaGetSymbolAddress(&pp, h_p);     cudaGetSymbolAddress(&pzc, h_zc);
    cudaGetSymbolAddress(&plog, g_logits);
    cudaGetSymbolAddress(&bxh, g_xh);   cudaGetSymbolAddress(&bxl, g_xl);
    cudaGetSymbolAddress(&bwrh, g_wrh); cudaGetSymbolAddress(&bwrl, g_wrl);

    // 1a. x -> fp16 + bf16 limbs in one read
    convx_kernel<<<(T_TOK * HD / 4) / 256, 256>>>((const float4*)x, (__half*)px,
                                                  (__nv_bfloat16*)bxh, (__nv_bfloat16*)bxl, T_TOK * HD / 4);
    // 1b. all six weight tensors -> fp16 in ONE launch (args by value: graph-safe)
    convall_kernel<<<CONV_BLOCKS, 256>>>(
        (const float4*)w_gate, (__half*)pwg,
        (const float4*)w_up,   (__half*)pwu,
        (const float4*)w_down, (__half*)pwc,
        (const float4*)shared_w_gate, (__half*)psgw,
        (const float4*)shared_w_up,   (__half*)psuw,
        (const float4*)shared_w_down, (__half*)pwc + (size_t)ID * HD);
    split_kernel<<<(HD * NE / 4) / 256, 256>>>((const float4*)w_router, (__nv_bfloat16*)bwrh, (__nv_bfloat16*)bwrl, HD * NE / 4);

    // 2. router path in bf16x3 (precision-sensitive: top-k selection)
    mix_kernel<<<1, 128>>>(amplitudes);
    hmma3_kernel<128><<<dim3(T_TOK / BM, 1), 512, SMEM_128>>>(
        (const __nv_bfloat16*)bxh, (const __nv_bfloat16*)bxl,
        (const __nv_bfloat16*)bwrh, (const __nv_bfloat16*)bwrl, (float*)plog, NE, HD);
    topk_kernel<<<T_TOK / 8, 256>>>(expert_scale);

    // 3. fused gate/up GEMM + silu: p = silu(x@Wg) * (x@Wu)
    hmma_gu_kernel<<<dim3(T_TOK / BM, KI / 128), 512, SMEM_GU>>>(
        (const __half*)px, (const __half*)pwg, (const __half*)pwu, (__half*)pp, KI, KI, HD);

    // 4. z = sum_k wk * p -> cols [0,ID) of zc
    moe_mix_kernel<<<dim3(ID / 512, T_TOK), 256>>>();

    // 5. fused shared expert -> cols [ID,KC) of zc
    hmma_gu_kernel<<<dim3(T_TOK / BM, I2 / 128), 512, SMEM_GU>>>(
        (const __half*)px, (const __half*)psgw, (const __half*)psuw,
        (__half*)pzc + ID, I2, KC, HD);

    // 6. combined down projection: out = [z|h] @ [Wd;Wsd]
    hmma1f_kernel<256><<<dim3(T_TOK / BM, HD / 256), 512, SMEM_S256>>>(
        (const __half*)pzc, (const __half*)pwc, out, HD, KC);
}

// round 17
// speedup vs baseline: 1.0610x; 1.0167x over previous
#include <cuda_runtime.h>
#include <cuda_bf16.h>
#include <cuda_fp16.h>
#include <math.h>
#include <float.h>
#include <stdint.h>

// ---------------- problem constants ----------------
#define T_TOK 8192
#define HD    2048
#define ID    1024
#define KQ    8
#define NE    128
#define KI    8192
#define I2    2048
#define KC    3072        // ID + I2 combined down-proj K

// ---------------- fp32 scratch ----------------
__device__ float g_logits[1048576];   // [T, NE] partial 0
__device__ float g_logits2[1048576];  // [T, NE] partial 1
__device__ float g_wk[65536];         // [T, KQ]
__device__ float g_mix[1024];         // [NE, KQ]

// ---------------- fp16 scratch ----------------
__device__ __half h_x[16777216];                    // x [T,HD]
__device__ __half h_wg[16777216];                   // w_gate [HD,KI]
__device__ __half h_wu[16777216];                   // w_up
__device__ __half h_sgw[4194304];                   // shared_w_gate [HD,I2]
__device__ __half h_suw[4194304];                   // shared_w_up
__device__ __half h_wc[6291456];                    // [w_down ; shared_w_down] [KC,HD]
__device__ __half h_p[67108864];                    // silu(gate)*up [T,KI]
__device__ __half h_zc[25165824];                   // [z | h] [T,KC]

// bf16 (router only)
__device__ __nv_bfloat16 g_xh[16777216], g_xl[16777216];
__device__ __nv_bfloat16 g_wrh[262144],  g_wrl[262144];

// ================= low-level helpers =================
__device__ __forceinline__ uint32_t smem_u32(const void* p) {
    uint32_t a;
    asm("{ .reg .u64 t; cvta.to.shared.u64 t, %1; cvt.u32.u64 %0, t; }" : "=r"(a) : "l"(p));
    return a;
}
__device__ __forceinline__ void cp16(uint32_t dst, const void* src) {
    asm volatile("cp.async.cg.shared.global [%0], [%1], 16;" :: "r"(dst), "l"(src));
}
__device__ __forceinline__ void cp_commit() {
    asm volatile("cp.async.commit_group;" ::: "memory");
}
template<int N> __device__ __forceinline__ void cp_wait() {
    asm volatile("cp.async.wait_group %0;" :: "n"(N) : "memory");
}
__device__ __forceinline__ void ldsm4(uint32_t* r, uint32_t addr) {
    asm volatile("ldmatrix.sync.aligned.m8n8.x4.shared.b16 {%0,%1,%2,%3}, [%4];"
                 : "=r"(r[0]), "=r"(r[1]), "=r"(r[2]), "=r"(r[3]) : "r"(addr));
}
__device__ __forceinline__ void ldsm4t(uint32_t* r, uint32_t addr) {
    asm volatile("ldmatrix.sync.aligned.m8n8.x4.trans.shared.b16 {%0,%1,%2,%3}, [%4];"
                 : "=r"(r[0]), "=r"(r[1]), "=r"(r[2]), "=r"(r[3]) : "r"(addr));
}
__device__ __forceinline__ void mma_bf16(float* d, const uint32_t* a, uint32_t b0, uint32_t b1) {
    asm volatile("mma.sync.aligned.m16n8k16.row.col.f32.bf16.bf16.f32 "
                 "{%0,%1,%2,%3}, {%4,%5,%6,%7}, {%8,%9}, {%0,%1,%2,%3};"
                 : "+f"(d[0]), "+f"(d[1]), "+f"(d[2]), "+f"(d[3])
                 : "r"(a[0]), "r"(a[1]), "r"(a[2]), "r"(a[3]), "r"(b0), "r"(b1));
}
__device__ __forceinline__ void mma_f16(float* d, const uint32_t* a, uint32_t b0, uint32_t b1) {
    asm volatile("mma.sync.aligned.m16n8k16.row.col.f32.f16.f16.f32 "
                 "{%0,%1,%2,%3}, {%4,%5,%6,%7}, {%8,%9}, {%0,%1,%2,%3};"
                 : "+f"(d[0]), "+f"(d[1]), "+f"(d[2]), "+f"(d[3])
                 : "r"(a[0]), "r"(a[1]), "r"(a[2]), "r"(a[3]), "r"(b0), "r"(b1));
}

__device__ __forceinline__ float silu_mul(float g, float u) {
    return (g / (1.f + expf(-g))) * u;
}

#define BM 128
#define BK 64
#define A_STR 144
#define SA_HALF (BM * A_STR)

// ================= fused dual-B GEMM: P = silu(A@Bg) * (A@Bu), fp16 out =================
#define GB_STR 272
#define GSB (BK * GB_STR)
#define GSTAGE (SA_HALF + 2 * GSB)
#define SMEM_GU (2 * GSTAGE)

__global__ __launch_bounds__(512, 1)
void hmma_gu_kernel(const __half* __restrict__ A, const __half* __restrict__ Bg,
                    const __half* __restrict__ Bu, __half* __restrict__ P,
                    int NB, int NP, int Kd)
{
    extern __shared__ char smem[];
    const uint32_t sb = smem_u32(smem);
    const int tid  = threadIdx.x;
    const int lane = tid & 31;
    const int wid  = tid >> 5;
    const int wr   = wid & 3;
    const int wc   = wid >> 2;
    const int row0 = blockIdx.x * BM;
    const int col0 = blockIdx.y * 128;
    const int nch  = Kd >> 6;

    float accg[2][4][4], accu[2][4][4];
#pragma unroll
    for (int i = 0; i < 2; i++)
#pragma unroll
        for (int j = 0; j < 4; j++)
#pragma unroll
            for (int q = 0; q < 4; q++) { accg[i][j][q] = 0.f; accu[i][j][q] = 0.f; }

    auto load_stage = [&](int stg, int k0) {
        uint32_t s0 = sb + stg * GSTAGE;
#pragma unroll
        for (int it = 0; it < 2; it++) {
            int idx = it * 512 + tid;
            int r = idx >> 3, c = idx & 7;
            cp16(s0 + r * A_STR + c * 16, A + (size_t)(row0 + r) * Kd + k0 + c * 8);
        }
#pragma unroll
        for (int it = 0; it < 2; it++) {
            int idx = it * 512 + tid;
            int r = idx >> 4, c = idx & 15;
            size_t go = (size_t)(k0 + r) * NB + col0 + c * 8;
            uint32_t d = s0 + SA_HALF + r * GB_STR + c * 16;
            cp16(d, Bg + go);
            cp16(d + GSB, Bu + go);
        }
        cp_commit();
    };

    load_stage(0, 0);

    const int a_row  = wr * 32 + (lane & 15);
    const int a_colb = (lane >> 4) << 4;
    const int b_row  = lane & 15;
    const int b_colb = (wc * 32 + ((lane >> 4) << 3)) * 2;

    for (int ch = 0; ch < nch; ch++) {
        cp_wait<0>();
        __syncthreads();
        if (ch + 1 < nch) load_stage((ch + 1) & 1, (ch + 1) << 6);

        uint32_t sA  = sb + (ch & 1) * GSTAGE;
        uint32_t sBg = sA + SA_HALF;
        uint32_t sBu = sBg + GSB;

#pragma unroll
        for (int ks = 0; ks < 4; ks++) {
            const int k16 = ks << 4;
            uint32_t Af[2][4];
#pragma unroll
            for (int mi = 0; mi < 2; mi++)
                ldsm4(Af[mi], sA + (a_row + mi * 16) * A_STR + k16 * 2 + a_colb);
#pragma unroll
            for (int nh = 0; nh < 2; nh++) {
                uint32_t Bgf[4], Buf[4];
                uint32_t bo = (b_row + k16) * GB_STR + b_colb + nh * 32;
                ldsm4t(Bgf, sBg + bo);
                ldsm4t(Buf, sBu + bo);
#pragma unroll
                for (int mi = 0; mi < 2; mi++)
#pragma unroll
                    for (int q = 0; q < 2; q++) {
                        mma_f16(accg[mi][nh * 2 + q], Af[mi], Bgf[q * 2], Bgf[q * 2 + 1]);
                        mma_f16(accu[mi][nh * 2 + q], Af[mi], Buf[q * 2], Buf[q * 2 + 1]);
                    }
            }
        }
    }

    const int er = row0 + wr * 32 + (lane >> 2);
    const int ec = col0 + wc * 32 + (lane & 3) * 2;
#pragma unroll
    for (int mi = 0; mi < 2; mi++)
#pragma unroll
        for (int ni = 0; ni < 4; ni++) {
            __half* p0 = P + (size_t)(er + mi * 16) * NP + ec + ni * 8;
            __half* p1 = p0 + 8 * NP;
            *(__half2*)p0 = __floats2half2_rn(silu_mul(accg[mi][ni][0], accu[mi][ni][0]),
                                              silu_mul(accg[mi][ni][1], accu[mi][ni][1]));
            *(__half2*)p1 = __floats2half2_rn(silu_mul(accg[mi][ni][2], accu[mi][ni][2]),
                                              silu_mul(accg[mi][ni][3], accu[mi][ni][3]));
        }
}

// ================= fp16 single-pass GEMM, fp32 output, 2-stage =================
template<int BN_T>
__global__ __launch_bounds__(512, 1)
void hmma1f_kernel(const __half* __restrict__ A, const __half* __restrict__ B,
                   float* __restrict__ C, int N, int Kd)
{
    constexpr int WN      = BN_T / 4;
    constexpr int NH      = BN_T / 64;
    constexpr int B_STR_T = BN_T * 2 + 16;
    constexpr int SB      = BK * B_STR_T;
    constexpr int STAGEB  = SA_HALF + SB;
    constexpr int NBCH    = BN_T / 8;
    constexpr int B_ITERS = (BK * NBCH) / 512;

    extern __shared__ char smem[];
    const uint32_t sb = smem_u32(smem);
    const int tid  = threadIdx.x;
    const int lane = tid & 31;
    const int wid  = tid >> 5;
    const int wr   = wid & 3;
    const int wc   = wid >> 2;
    const int row0 = blockIdx.x * BM;
    const int col0 = blockIdx.y * BN_T;
    const int nch  = Kd >> 6;

    float accf[2][2 * NH][4];
#pragma unroll
    for (int i = 0; i < 2; i++)
#pragma unroll
        for (int j = 0; j < 2 * NH; j++)
#pragma unroll
            for (int q = 0; q < 4; q++) accf[i][j][q] = 0.f;

    auto load_stage = [&](int stg, int k0) {
        uint32_t s0 = sb + stg * STAGEB;
#pragma unroll
        for (int it = 0; it < 2; it++) {
            int idx = it * 512 + tid;
            int r = idx >> 3, c = idx & 7;
            cp16(s0 + r * A_STR + c * 16, A + (size_t)(row0 + r) * Kd + k0 + c * 8);
        }
#pragma unroll
        for (int it = 0; it < B_ITERS; it++) {
            int idx = it * 512 + tid;
            int r = idx / NBCH, c = idx % NBCH;
            cp16(s0 + SA_HALF + r * B_STR_T + c * 16, B + (size_t)(k0 + r) * N + col0 + c * 8);
        }
        cp_commit();
    };

    load_stage(0, 0);

    const int a_row  = wr * 32 + (lane & 15);
    const int a_colb = (lane >> 4) << 4;
    const int b_row  = lane & 15;
    const int b_colb = (wc * WN + ((lane >> 4) << 3)) * 2;

    for (int ch = 0; ch < nch; ch++) {
        cp_wait<0>();
        __syncthreads();
        if (ch + 1 < nch) load_stage((ch + 1) & 1, (ch + 1) << 6);

        uint32_t sA = sb + (ch & 1) * STAGEB;
        uint32_t sB = sA + SA_HALF;

#pragma unroll
        for (int ks = 0; ks < 4; ks++) {
            const int k16 = ks << 4;
            uint32_t Af[2][4];
#pragma unroll
            for (int mi = 0; mi < 2; mi++)
                ldsm4(Af[mi], sA + (a_row + mi * 16) * A_STR + k16 * 2 + a_colb);
#pragma unroll
            for (int nh = 0; nh < NH; nh++) {
                uint32_t Bf[4];
                ldsm4t(Bf, sB + (b_row + k16) * B_STR_T + b_colb + nh * 32);
#pragma unroll
                for (int mi = 0; mi < 2; mi++)
#pragma unroll
                    for (int q = 0; q < 2; q++)
                        mma_f16(accf[mi][nh * 2 + q], Af[mi], Bf[q * 2], Bf[q * 2 + 1]);
            }
        }
    }

    const int er = row0 + wr * 32 + (lane >> 2);
    const int ec = col0 + wc * WN + (lane & 3) * 2;
#pragma unroll
    for (int mi = 0; mi < 2; mi++)
#pragma unroll
        for (int ni = 0; ni < 2 * NH; ni++) {
            float* p0 = C + (size_t)(er + mi * 16) * N + ec + ni * 8;
            float* p1 = p0 + 8 * N;
            *(float2*)p0 = make_float2(accf[mi][ni][0], accf[mi][ni][1]);
            *(float2*)p1 = make_float2(accf[mi][ni][2], accf[mi][ni][3]);
        }
}
#define SMEM_S256 (2 * (SA_HALF + BK * (256 * 2 + 16)))   // 104448

// ================= bf16 hi/lo 3-pass GEMM (router, split-K x2 via grid.z) =================
// Kd = K-half length (1024); lda = full row stride (HD); blockIdx.z selects half+output.
template<int BN_T>
__global__ __launch_bounds__(512, 1)
void hmma3_kernel(const __nv_bfloat16* __restrict__ Ah, const __nv_bfloat16* __restrict__ Al,
                  const __nv_bfloat16* __restrict__ Bh, const __nv_bfloat16* __restrict__ Bl,
                  float* __restrict__ C0, float* __restrict__ C1,
                  int N, int Kd, int lda)
{
    constexpr int WN      = BN_T / 4;
    constexpr int NH      = BN_T / 64;
    constexpr int B_STR_T = BN_T * 2 + 16;
    constexpr int SB_HALF = BK * B_STR_T;
    constexpr int STAGEB  = 2 * SA_HALF + 2 * SB_HALF;
    constexpr int NBCH    = BN_T / 8;
    constexpr int B_ITERS = (BK * NBCH) / 512;

    const int kz = blockIdx.z;
    const int kbase = kz * Kd;
    float* C = kz ? C1 : C0;

    extern __shared__ char smem[];
    const uint32_t sb = smem_u32(smem);
    const int tid  = threadIdx.x;
    const int lane = tid & 31;
    const int wid  = tid >> 5;
    const int wr   = wid & 3;
    const int wc   = wid >> 2;
    const int row0 = blockIdx.x * BM;
    const int col0 = blockIdx.y * BN_T;
    const int nch  = Kd >> 6;

    float accf[2][2 * NH][4];
#pragma unroll
    for (int i = 0; i < 2; i++)
#pragma unroll
        for (int j = 0; j < 2 * NH; j++)
#pragma unroll
            for (int q = 0; q < 4; q++) accf[i][j][q] = 0.f;

    auto load_stage = [&](int stg, int k0) {
        uint32_t s0 = sb + stg * STAGEB;
#pragma unroll
        for (int it = 0; it < 2; it++) {
            int idx = it * 512 + tid;
            int r = idx >> 3, c = idx & 7;
            const __nv_bfloat16* gh = Ah + (size_t)(row0 + r) * lda + kbase + k0 + c * 8;
            const __nv_bfloat16* gl = Al + (size_t)(row0 + r) * lda + kbase + k0 + c * 8;
            uint32_t d = s0 + r * A_STR + c * 16;
            cp16(d, gh);
            cp16(d + SA_HALF, gl);
        }
#pragma unroll
        for (int it = 0; it < B_ITERS; it++) {
            int idx = it * 512 + tid;
            int r = idx / NBCH, c = idx % NBCH;
            const __nv_bfloat16* gh = Bh + (size_t)(kbase + k0 + r) * N + col0 + c * 8;
            const __nv_bfloat16* gl = Bl + (size_t)(kbase + k0 + r) * N + col0 + c * 8;
            uint32_t d = s0 + 2 * SA_HALF + r * B_STR_T + c * 16;
            cp16(d, gh);
            cp16(d + SB_HALF, gl);
        }
        cp_commit();
    };

    load_stage(0, 0);

    const int a_row  = wr * 32 + (lane & 15);
    const int a_colb = (lane >> 4) << 4;
    const int b_row  = lane & 15;
    const int b_colb = (wc * WN + ((lane >> 4) << 3)) * 2;

    for (int ch = 0; ch < nch; ch++) {
        cp_wait<0>();
        __syncthreads();
        if (ch + 1 < nch) load_stage((ch + 1) & 1, (ch + 1) << 6);

        uint32_t sA = sb + (ch & 1) * STAGEB;
        uint32_t sB = sA + 2 * SA_HALF;

#pragma unroll
        for (int ks = 0; ks < 4; ks++) {
            const int k16 = ks << 4;
            uint32_t Ahf[2][4], Alf[2][4];
#pragma unroll
            for (int mi = 0; mi < 2; mi++) {
                uint32_t ad = sA + (a_row + mi * 16) * A_STR + k16 * 2 + a_colb;
                ldsm4(Ahf[mi], ad);
                ldsm4(Alf[mi], ad + SA_HALF);
            }
#pragma unroll
            for (int nh = 0; nh < NH; nh++) {
                uint32_t Bhf[4], Blf[4];
                uint32_t bd = sB + (b_row + k16) * B_STR_T + b_colb + nh * 32;
                ldsm4t(Bhf, bd);
                ldsm4t(Blf, bd + SB_HALF);
#pragma unroll
                for (int mi = 0; mi < 2; mi++)
#pragma unroll
                    for (int q = 0; q < 2; q++) {
                        float* d = accf[mi][nh * 2 + q];
                        mma_bf16(d, Ahf[mi], Bhf[q * 2], Bhf[q * 2 + 1]);
                        mma_bf16(d, Alf[mi], Bhf[q * 2], Bhf[q * 2 + 1]);
                        mma_bf16(d, Ahf[mi], Blf[q * 2], Blf[q * 2 + 1]);
                    }
            }
        }
    }

    const int er = row0 + wr * 32 + (lane >> 2);
    const int ec = col0 + wc * WN + (lane & 3) * 2;
#pragma unroll
    for (int mi = 0; mi < 2; mi++)
#pragma unroll
        for (int ni = 0; ni < 2 * NH; ni++) {
            float* p0 = C + (size_t)(er + mi * 16) * N + ec + ni * 8;
            float* p1 = p0 + 8 * N;
            *(float2*)p0 = make_float2(accf[mi][ni][0], accf[mi][ni][1]);
            *(float2*)p1 = make_float2(accf[mi][ni][2], accf[mi][ni][3]);
        }
}
#define SMEM_128 (2 * (2 * SA_HALF + 2 * (BK * (128 * 2 + 16))))

// ================= conversions =================
__global__ void convx_kernel(const float4* __restrict__ src, __half* __restrict__ xh,
                             __nv_bfloat16* __restrict__ bh, __nv_bfloat16* __restrict__ bl, int n4)
{
    int i = blockIdx.x * 256 + threadIdx.x;
    if (i >= n4) return;
    float4 v = src[i];
    __half2* dp = (__half2*)(xh + i * 4);
    dp[0] = __floats2half2_rn(v.x, v.y);
    dp[1] = __floats2half2_rn(v.z, v.w);
    __nv_bfloat16 h0 = __float2bfloat16_rn(v.x), h1 = __float2bfloat16_rn(v.y);
    __nv_bfloat16 h2 = __float2bfloat16_rn(v.z), h3 = __float2bfloat16_rn(v.w);
    __nv_bfloat162 hh0 = {h0, h1}, hh1 = {h2, h3};
    __nv_bfloat162 ll0 = {__float2bfloat16_rn(v.x - __bfloat162float(h0)),
                          __float2bfloat16_rn(v.y - __bfloat162float(h1))};
    __nv_bfloat162 ll1 = {__float2bfloat16_rn(v.z - __bfloat162float(h2)),
                          __float2bfloat16_rn(v.w - __bfloat162float(h3))};
    *(__nv_bfloat162*)(bh + i * 4)     = hh0;
    *(__nv_bfloat162*)(bh + i * 4 + 2) = hh1;
    *(__nv_bfloat162*)(bl + i * 4)     = ll0;
    *(__nv_bfloat162*)(bl + i * 4 + 2) = ll1;
}

// one launch converts all six weight tensors; args by value (graph-safe)
#define N4_BIG   (HD * KI / 4)
#define N4_SMALL (HD * I2 / 4)
#define BLK_BIG   (N4_BIG / 256)
#define BLK_SMALL (N4_SMALL / 256)

__global__ void convall_kernel(const float4* s0, __half* d0,
                               const float4* s1, __half* d1,
                               const float4* s2, __half* d2,
                               const float4* s3, __half* d3,
                               const float4* s4, __half* d4,
                               const float4* s5, __half* d5)
{
    int b = blockIdx.x;
    const float4* src;
    __half* dst;
    int i;
    if (b < BLK_BIG)                        { src = s0; dst = d0; i = b * 256 + threadIdx.x; }
    else if (b < 2 * BLK_BIG)               { src = s1; dst = d1; i = (b - 2 * BLK_BIG + BLK_BIG) * 256 + threadIdx.x; }
    else if (b < 2 * BLK_BIG + BLK_SMALL/2) { src = s2; dst = d2; i = (b - 2 * BLK_BIG) * 256 + threadIdx.x; }
    else if (b < 2 * BLK_BIG + BLK_SMALL/2 + BLK_SMALL) { src = s3; dst = d3; i = (b - 2 * BLK_BIG - BLK_SMALL/2) * 256 + threadIdx.x; }
    else if (b < 2 * BLK_BIG + BLK_SMALL/2 + 2 * BLK_SMALL) { src = s4; dst = d4; i = (b - 2 * BLK_BIG - BLK_SMALL/2 - BLK_SMALL) * 256 + threadIdx.x; }
    else                                    { src = s5; dst = d5; i = (b - 2 * BLK_BIG - BLK_SMALL/2 - 2 * BLK_SMALL) * 256 + threadIdx.x; }
    float4 v = src[i];
    __half2* dp = (__half2*)(dst + (size_t)i * 4);
    dp[0] = __floats2half2_rn(v.x, v.y);
    dp[1] = __floats2half2_rn(v.z, v.w);
}
#define CONV_BLOCKS (2 * BLK_BIG + BLK_SMALL/2 + 3 * BLK_SMALL)

__global__ void split_kernel(const float4* __restrict__ src,
                             __nv_bfloat16* __restrict__ hi,
                             __nv_bfloat16* __restrict__ lo, int n4)
{
    int i = blockIdx.x * 256 + threadIdx.x;
    if (i >= n4) return;
    float4 v = src[i];
    __nv_bfloat16 h0 = __float2bfloat16_rn(v.x), h1 = __float2bfloat16_rn(v.y);
    __nv_bfloat16 h2 = __float2bfloat16_rn(v.z), h3 = __float2bfloat16_rn(v.w);
    __nv_bfloat162 hh0 = {h0, h1}, hh1 = {h2, h3};
    __nv_bfloat162 ll0 = {__float2bfloat16_rn(v.x - __bfloat162float(h0)),
                          __float2bfloat16_rn(v.y - __bfloat162float(h1))};
    __nv_bfloat162 ll1 = {__float2bfloat16_rn(v.z - __bfloat162float(h2)),
                          __float2bfloat16_rn(v.w - __bfloat162float(h3))};
    *(__nv_bfloat162*)(hi + i * 4)     = hh0;
    *(__nv_bfloat162*)(hi + i * 4 + 2) = hh1;
    *(__nv_bfloat162*)(lo + i * 4)     = ll0;
    *(__nv_bfloat162*)(lo + i * 4 + 2) = ll1;
}

// ================= amplitudes -> normalized mix =================
__global__ void mix_kernel(const float* __restrict__ amp)
{
    int e = threadIdx.x;
    if (e >= NE) return;
    float p[KQ];
    float s = 0.f;
#pragma unroll
    for (int k = 0; k < KQ; k++) {
        float a0 = amp[(e * KQ + k) * 2 + 0];
        float a1 = amp[(e * KQ + k) * 2 + 1];
        p[k] = a0 * a0 + a1 * a1;
        s += p[k];
    }
    float inv = 1.f / (s + 1e-8f);
#pragma unroll
    for (int k = 0; k < KQ; k++) g_mix[e * KQ + k] = p[k] * inv;
}

// ================= softmax + top-4 + collapse (sums two logit partials) =================
__global__ void topk_kernel(const float* __restrict__ expert_scale)
{
    int lane = threadIdx.x & 31;
    int warp = threadIdx.x >> 5;
    int t = blockIdx.x * 8 + warp;
    const float* l0 = g_logits  + (size_t)t * NE;
    const float* l1 = g_logits2 + (size_t)t * NE;

    float v[4];
#pragma unroll
    for (int j = 0; j < 4; j++) v[j] = l0[lane + 32 * j] + l1[lane + 32 * j];

    float m = fmaxf(fmaxf(v[0], v[1]), fmaxf(v[2], v[3]));
#pragma unroll
    for (int o = 16; o; o >>= 1) m = fmaxf(m, __shfl_xor_sync(0xffffffffu, m, o));

    float D = 0.f;
#pragma unroll
    for (int j = 0; j < 4; j++) D += expf(v[j] - m);
#pragma unroll
    for (int o = 16; o; o >>= 1) D += __shfl_xor_sync(0xffffffffu, D, o);

    float lv[4] = {v[0], v[1], v[2], v[3]};
    float selv[4];
    int   seli[4];
#pragma unroll
    for (int it = 0; it < 4; it++) {
        float bv = -FLT_MAX;
        int   bi = NE;
#pragma unroll
        for (int j = 0; j < 4; j++) {
            int e = lane + 32 * j;
            if (lv[j] > bv) { bv = lv[j]; bi = e; }
        }
#pragma unroll
        for (int o = 16; o; o >>= 1) {
            float ov = __shfl_xor_sync(0xffffffffu, bv, o);
            int   oi = __shfl_xor_sync(0xffffffffu, bi, o);
            if (ov > bv || (ov == bv && oi < bi)) { bv = ov; bi = oi; }
        }
        selv[it] = bv;
        seli[it] = bi;
        if ((bi & 31) == lane) lv[bi >> 5] = -FLT_MAX;
    }

    float ew[4];
    float S = 0.f;
#pragma unroll
    for (int it = 0; it < 4; it++) { ew[it] = expf(selv[it] - m); S += ew[it]; }
    float denom = S + 1e-8f * D;

    if (lane < KQ) {
        float acc = 0.f;
#pragma unroll
        for (int it = 0; it < 4; it++)
            acc += (ew[it] / denom) * expert_scale[seli[it]] * g_mix[seli[it] * KQ + lane];
        g_wk[t * KQ + lane] = acc;
    }
}

// ================= z = sum_k wk * p[t,k,i]  -> cols 0..ID-1 of h_zc (uint4) =================
__global__ void moe_mix_kernel()
{
    int t = blockIdx.x;
    int i = threadIdx.x * 8;                 // 128 threads * 8 = 1024 cols
    __shared__ float w[KQ];
    if (threadIdx.x < KQ) w[threadIdx.x] = g_wk[t * KQ + threadIdx.x];
    __syncthreads();
    float a[8];
#pragma unroll
    for (int j = 0; j < 8; j++) a[j] = 0.f;
#pragma unroll
    for (int k = 0; k < KQ; k++) {
        uint4 pv = *(const uint4*)(h_p + (size_t)t * KI + k * ID + i);
        const __half2* ph = (const __half2*)&pv;
#pragma unroll
        for (int j = 0; j < 4; j++) {
            a[2 * j]     += w[k] * __low2float(ph[j]);
            a[2 * j + 1] += w[k] * __high2float(ph[j]);
        }
    }
    uint4 ov;
    __half2* oh = (__half2*)&ov;
#pragma unroll
    for (int j = 0; j < 4; j++)
        oh[j] = __floats2half2_rn(a[2 * j], a[2 * j + 1]);
    *(uint4*)(h_zc + (size_t)t * KC + i) = ov;
}

// ================= host side =================
extern "C" void kernel_launch(void* const* d_in, const int* in_sizes, int n_in,
                              void* d_out, int out_size)
{
    const float* x             = (const float*)d_in[0];
    const float* w_router      = (const float*)d_in[1];
    const float* w_gate        = (const float*)d_in[2];
    const float* w_up          = (const float*)d_in[3];
    const float* w_down        = (const float*)d_in[4];
    const float* amplitudes    = (const float*)d_in[5];
    const float* expert_scale  = (const float*)d_in[6];
    const float* shared_w_gate = (const float*)d_in[7];
    const float* shared_w_up   = (const float*)d_in[8];
    const float* shared_w_down = (const float*)d_in[9];
    float* out = (float*)d_out;

    cudaFuncSetAttribute(hmma_gu_kernel, cudaFuncAttributeMaxDynamicSharedMemorySize, SMEM_GU);
    cudaFuncSetAttribute(hmma1f_kernel<256>, cudaFuncAttributeMaxDynamicSharedMemorySize, SMEM_S256);
    cudaFuncSetAttribute(hmma3_kernel<128>, cudaFuncAttributeMaxDynamicSharedMemorySize, SMEM_128);

    void *px, *pwg, *pwu, *psgw, *psuw, *pwc;
    void *pp, *pzc, *plog, *plog2;
    void *bxh, *bxl, *bwrh, *bwrl;
    cudaGetSymbolAddress(&px, h_x);
    cudaGetSymbolAddress(&pwg, h_wg);   cudaGetSymbolAddress(&pwu, h_wu);
    cudaGetSymbolAddress(&psgw, h_sgw); cudaGetSymbolAddress(&psuw, h_suw);
    cudaGetSymbolAddress(&pwc, h_wc);
    cudaGetSymbolAddress(&pp, h_p);     cudaGetSymbolAddress(&pzc, h_zc);
    cudaGetSymbolAddress(&plog, g_logits); cudaGetSymbolAddress(&plog2, g_logits2);
    cudaGetSymbolAddress(&bxh, g_xh);   cudaGetSymbolAddress(&bxl, g_xl);
    cudaGetSymbolAddress(&bwrh, g_wrh); cudaGetSymbolAddress(&bwrl, g_wrl);

    // 1a. x -> fp16 + bf16 limbs in one read
    convx_kernel<<<(T_TOK * HD / 4) / 256, 256>>>((const float4*)x, (__half*)px,
                                                  (__nv_bfloat16*)bxh, (__nv_bfloat16*)bxl, T_TOK * HD / 4);
    // 1b. all six weight tensors -> fp16 in ONE launch
    convall_kernel<<<CONV_BLOCKS, 256>>>(
        (const float4*)w_gate, (__half*)pwg,
        (const float4*)w_up,   (__half*)pwu,
        (const float4*)w_down, (__half*)pwc,
        (const float4*)shared_w_gate, (__half*)psgw,
        (const float4*)shared_w_up,   (__half*)psuw,
        (const float4*)shared_w_down, (__half*)pwc + (size_t)ID * HD);
    split_kernel<<<(HD * NE / 4) / 256, 256>>>((const float4*)w_router, (__nv_bfloat16*)bwrh, (__nv_bfloat16*)bwrl, HD * NE / 4);

    // 2. router path in bf16x3, split-K x2 (grid.z) -> two fp32 partials
    mix_kernel<<<1, 128>>>(amplitudes);
    hmma3_kernel<128><<<dim3(T_TOK / BM, 1, 2), 512, SMEM_128>>>(
        (const __nv_bfloat16*)bxh, (const __nv_bfloat16*)bxl,
        (const __nv_bfloat16*)bwrh, (const __nv_bfloat16*)bwrl,
        (float*)plog, (float*)plog2, NE, HD / 2, HD);
    topk_kernel<<<T_TOK / 8, 256>>>(expert_scale);

    // 3. fused gate/up GEMM + silu: p = silu(x@Wg) * (x@Wu)
    hmma_gu_kernel<<<dim3(T_TOK / BM, KI / 128), 512, SMEM_GU>>>(
        (const __half*)px, (const __half*)pwg, (const __half*)pwu, (__half*)pp, KI, KI, HD);

    // 4. z = sum_k wk * p -> cols [0,ID) of zc
    moe_mix_kernel<<<T_TOK, 128>>>();

    // 5. fused shared expert -> cols [ID,KC) of zc
    hmma_gu_kernel<<<dim3(T_TOK / BM, I2 / 128), 512, SMEM_GU>>>(
        (const __half*)px, (const __half*)psgw, (const __half*)psuw,
        (__half*)pzc + ID, I2, KC, HD);

    // 6. combined down projection: out = [z|h] @ [Wd;Wsd]
    hmma1f_kernel<256><<<dim3(T_TOK / BM, HD / 256), 512, SMEM_S256>>>(
        (const __half*)pzc, (const __half*)pwc, out, HD, KC);
}